// round 1
// baseline (speedup 1.0000x reference)
#include <cuda_runtime.h>
#include <math.h>
#include <stdint.h>

// ---------------- problem constants ----------------
#define BBATCH 4
#define TT     24
#define NST    128
#define FINF   64
#define CC     256
#define LL     3
#define KK     3
#define GHH    2
#define NHH    4
#define EE     1024
#define NG     (BBATCH*TT)        // 96 graphs
#define NNODE  (NG*NST)           // 12288 nodes
#define EBASE  (NG*EE)            // 98304 batched edges (self loops separate)

// ---------------- static scratch (no allocs allowed) ----------------
__device__ int d_csr_ptr[NST+1];
__device__ int d_csr_eid[EE];

#define OFF_H    ((size_t)0)
#define OFF_Y    (OFF_H    + (size_t)NNODE*CC)
#define OFF_SKIP (OFF_Y    + (size_t)NNODE*CC)
#define OFF_XL   (OFF_SKIP + (size_t)NNODE*CC)
#define OFF_XR   (OFF_XL   + (size_t)NNODE*GHH*CC)
#define OFF_Q    (OFF_XR   + (size_t)NNODE*GHH*CC)
#define OFF_K    (OFF_Q    + (size_t)NNODE*CC)
#define OFF_V    (OFF_K    + (size_t)NNODE*CC)
#define OFF_AO   (OFF_V    + (size_t)NNODE*CC)
#define OFF_HREF (OFF_AO   + (size_t)NNODE*CC)
#define OFF_ELOG (OFF_HREF + (size_t)NNODE*CC)
#define OFF_SLOG (OFF_ELOG + (size_t)EBASE*GHH)
#define OFF_WT   (OFF_SLOG + (size_t)NNODE*GHH)
#define TOTF     (OFF_WT   + (size_t)KK*CC*CC)
__device__ float d_buf[TOTF];

// ---------------- deterministic CSR of base graph ----------------
__global__ void build_csr_kernel(const int* __restrict__ edge) {
    const int* dst = edge + EE;
    int n = threadIdx.x;             // 0..127
    __shared__ int counts[NST];
    int cnt = 0;
    for (int e = 0; e < EE; e++) if (dst[e] == n) cnt++;
    counts[n] = cnt;
    __syncthreads();
    if (n == 0) {
        int s = 0;
        for (int i = 0; i < NST; i++) { d_csr_ptr[i] = s; s += counts[i]; }
        d_csr_ptr[NST] = s;
    }
    __syncthreads();
    int p = d_csr_ptr[n];
    for (int e = 0; e < EE; e++) if (dst[e] == n) d_csr_eid[p++] = e;  // stable order
}

// ---------------- generic fp32 GEMM: C = act(A[M,K] @ B[K,N] + bias) ----------------
template<int ACT>
__global__ void __launch_bounds__(256) gemm_kernel(
    const float* __restrict__ A, const float* __restrict__ B,
    const float* __restrict__ bias, float* __restrict__ C,
    int M, int N, int Kd)
{
    __shared__ float As[16][68];
    __shared__ float Bs[16][68];
    int tid = threadIdx.x;
    int bm = blockIdx.y << 6, bn = blockIdx.x << 6;
    int tx = tid & 15, ty = tid >> 4;
    int arow = tid >> 2, akq = (tid & 3) << 2;
    int brow = tid >> 4, bnq = (tid & 15) << 2;
    const float* Ap = A + (size_t)(bm + arow) * Kd + akq;
    const float* Bp = B + (size_t)brow * N + bn + bnq;
    float acc[4][4];
#pragma unroll
    for (int i = 0; i < 4; i++)
#pragma unroll
        for (int j = 0; j < 4; j++) acc[i][j] = 0.f;

    for (int k0 = 0; k0 < Kd; k0 += 16) {
        float4 a4 = *(const float4*)(Ap + k0);
        As[akq+0][arow] = a4.x; As[akq+1][arow] = a4.y;
        As[akq+2][arow] = a4.z; As[akq+3][arow] = a4.w;
        *(float4*)&Bs[brow][bnq] = *(const float4*)(Bp + (size_t)k0 * N);
        __syncthreads();
#pragma unroll
        for (int k = 0; k < 16; k++) {
            float4 av = *(const float4*)&As[k][ty << 2];
            float4 bv = *(const float4*)&Bs[k][tx << 2];
            acc[0][0] = fmaf(av.x, bv.x, acc[0][0]);
            acc[0][1] = fmaf(av.x, bv.y, acc[0][1]);
            acc[0][2] = fmaf(av.x, bv.z, acc[0][2]);
            acc[0][3] = fmaf(av.x, bv.w, acc[0][3]);
            acc[1][0] = fmaf(av.y, bv.x, acc[1][0]);
            acc[1][1] = fmaf(av.y, bv.y, acc[1][1]);
            acc[1][2] = fmaf(av.y, bv.z, acc[1][2]);
            acc[1][3] = fmaf(av.y, bv.w, acc[1][3]);
            acc[2][0] = fmaf(av.z, bv.x, acc[2][0]);
            acc[2][1] = fmaf(av.z, bv.y, acc[2][1]);
            acc[2][2] = fmaf(av.z, bv.z, acc[2][2]);
            acc[2][3] = fmaf(av.z, bv.w, acc[2][3]);
            acc[3][0] = fmaf(av.w, bv.x, acc[3][0]);
            acc[3][1] = fmaf(av.w, bv.y, acc[3][1]);
            acc[3][2] = fmaf(av.w, bv.z, acc[3][2]);
            acc[3][3] = fmaf(av.w, bv.w, acc[3][3]);
        }
        __syncthreads();
    }
#pragma unroll
    for (int i = 0; i < 4; i++) {
        int m = bm + (ty << 2) + i;
#pragma unroll
        for (int j = 0; j < 4; j++) {
            int n = bn + (tx << 2) + j;
            float v = acc[i][j];
            if (bias) v += bias[n];
            if (ACT == 1) v = fmaxf(v, 0.f);
            C[(size_t)m * N + n] = v;
        }
    }
}

// ---------------- dilated causal conv as gathered GEMM (K = 3*256), ReLU ----------------
__global__ void __launch_bounds__(256) conv_gemm_kernel(
    const float* __restrict__ H, const float* __restrict__ Bw,
    const float* __restrict__ bias, float* __restrict__ C, int dil)
{
    const int N = CC, Kd = KK * CC;
    __shared__ float As[16][68];
    __shared__ float Bs[16][68];
    int tid = threadIdx.x;
    int bm = blockIdx.y << 6, bn = blockIdx.x << 6;
    int tx = tid & 15, ty = tid >> 4;
    int arow = tid >> 2, akq = (tid & 3) << 2;
    int brow = tid >> 4, bnq = (tid & 15) << 2;
    int node = bm + arow;
    int t = (node >> 7) % TT;
    const float* Bp = Bw + (size_t)brow * N + bn + bnq;
    float acc[4][4];
#pragma unroll
    for (int i = 0; i < 4; i++)
#pragma unroll
        for (int j = 0; j < 4; j++) acc[i][j] = 0.f;

    for (int k0 = 0; k0 < Kd; k0 += 16) {
        int kg = k0 + akq;
        int tap = kg >> 8;                 // 0..2
        int shift = (2 - tap) * dil;       // causal left shift in time
        float4 a4 = make_float4(0.f, 0.f, 0.f, 0.f);
        if (t >= shift)
            a4 = *(const float4*)(H + (size_t)(node - (shift << 7)) * CC + (kg & 255));
        As[akq+0][arow] = a4.x; As[akq+1][arow] = a4.y;
        As[akq+2][arow] = a4.z; As[akq+3][arow] = a4.w;
        *(float4*)&Bs[brow][bnq] = *(const float4*)(Bp + (size_t)k0 * N);
        __syncthreads();
#pragma unroll
        for (int k = 0; k < 16; k++) {
            float4 av = *(const float4*)&As[k][ty << 2];
            float4 bv = *(const float4*)&Bs[k][tx << 2];
            acc[0][0] = fmaf(av.x, bv.x, acc[0][0]);
            acc[0][1] = fmaf(av.x, bv.y, acc[0][1]);
            acc[0][2] = fmaf(av.x, bv.z, acc[0][2]);
            acc[0][3] = fmaf(av.x, bv.w, acc[0][3]);
            acc[1][0] = fmaf(av.y, bv.x, acc[1][0]);
            acc[1][1] = fmaf(av.y, bv.y, acc[1][1]);
            acc[1][2] = fmaf(av.y, bv.z, acc[1][2]);
            acc[1][3] = fmaf(av.y, bv.w, acc[1][3]);
            acc[2][0] = fmaf(av.z, bv.x, acc[2][0]);
            acc[2][1] = fmaf(av.z, bv.y, acc[2][1]);
            acc[2][2] = fmaf(av.z, bv.z, acc[2][2]);
            acc[2][3] = fmaf(av.z, bv.w, acc[2][3]);
            acc[3][0] = fmaf(av.w, bv.x, acc[3][0]);
            acc[3][1] = fmaf(av.w, bv.y, acc[3][1]);
            acc[3][2] = fmaf(av.w, bv.z, acc[3][2]);
            acc[3][3] = fmaf(av.w, bv.w, acc[3][3]);
        }
        __syncthreads();
    }
#pragma unroll
    for (int i = 0; i < 4; i++) {
        int m = bm + (ty << 2) + i;
#pragma unroll
        for (int j = 0; j < 4; j++) {
            int n = bn + (tx << 2) + j;
            float v = fmaxf(acc[i][j] + bias[n], 0.f);
            C[(size_t)m * N + n] = v;
        }
    }
}

// ---------------- small elementwise kernels ----------------
__global__ void transpose_w_kernel(const float* __restrict__ w, float* __restrict__ wt) {
    int idx = blockIdx.x * 256 + threadIdx.x;        // < 3*256*256
    int cout = idx & 255;
    int cin  = (idx >> 8) & 255;
    int tap  = idx >> 16;
    wt[idx] = w[((cout << 8) + cin) * 3 + tap];
}

__global__ void add_emb_kernel(float* __restrict__ h,
                               const float* __restrict__ station,
                               const float* __restrict__ horizon) {
    int idx = blockIdx.x * 256 + threadIdx.x;
    int c = idx & 255;
    int i = idx >> 8;
    int n = i & 127;
    int t = (i >> 7) % TT;
    h[idx] += station[(n << 8) + c] + horizon[(t << 8) + c];
}

__global__ void add_skip_kernel(const float* __restrict__ y,
                                float* __restrict__ skip, float* __restrict__ h, int first) {
    int idx = blockIdx.x * 256 + threadIdx.x;
    float v = y[idx];
    skip[idx] = (first ? 0.f : skip[idx]) + v;
    h[idx] += v;
}

__global__ void add2_kernel(const float* __restrict__ a, const float* __restrict__ b,
                            float* __restrict__ o) {
    int idx = blockIdx.x * 256 + threadIdx.x;
    o[idx] = a[idx] + b[idx];
}

// ---------------- GAT edge logits: one 64-thread block per edge ----------------
__global__ void edge_logits_kernel(const float* __restrict__ xl, const float* __restrict__ xr,
                                   const float* __restrict__ att, const int* __restrict__ edge,
                                   float* __restrict__ elog, float* __restrict__ slog) {
    int e = blockIdx.x;
    int tid = threadIdx.x;
    int h = tid >> 5, lane = tid & 31;
    int si, di;
    float* outp;
    if (e < EBASE) {
        int g = e >> 10, ee = e & 1023;
        si = (g << 7) + edge[ee];
        di = (g << 7) + edge[EE + ee];
        outp = elog + (size_t)e * GHH;
    } else {
        int i = e - EBASE;
        si = di = i;
        outp = slog + (size_t)i * GHH;
    }
    const float* pl = xl + (size_t)si * (GHH*CC) + h * CC;
    const float* pr = xr + (size_t)di * (GHH*CC) + h * CC;
    const float* pa = att + h * CC;
    float s = 0.f;
    for (int c = lane; c < CC; c += 32) {
        float v = pl[c] + pr[c];
        v = v > 0.f ? v : 0.2f * v;
        s = fmaf(pa[c], v, s);
    }
#pragma unroll
    for (int o = 16; o; o >>= 1) s += __shfl_xor_sync(0xffffffffu, s, o);
    if (lane == 0) outp[h] = s;
}

// ---------------- GAT aggregate + residual + LayerNorm (one block per node) ------
__global__ void __launch_bounds__(256) gat_agg_ln_kernel(
    const int* __restrict__ edge, const float* __restrict__ xl,
    const float* __restrict__ elog, const float* __restrict__ slog,
    const float* __restrict__ gatb, const float* __restrict__ gamma,
    const float* __restrict__ beta, float* __restrict__ h)
{
    int i = blockIdx.x;
    int tid = threadIdx.x;           // 256
    int g = i >> 7, n = i & 127;
    int p0 = d_csr_ptr[n], p1 = d_csr_ptr[n+1];
    __shared__ float sh_m[2], sh_d[2];
    if (tid < 2) {
        int hh = tid;
        float m = slog[(size_t)i*GHH + hh];
        for (int p = p0; p < p1; p++)
            m = fmaxf(m, elog[((size_t)(g << 10) + d_csr_eid[p]) * GHH + hh]);
        float den = expf(slog[(size_t)i*GHH + hh] - m);
        for (int p = p0; p < p1; p++)
            den += expf(elog[((size_t)(g << 10) + d_csr_eid[p]) * GHH + hh] - m);
        sh_m[hh] = m; sh_d[hh] = den;
    }
    __syncthreads();
    int c = tid;
    float m0 = sh_m[0], m1 = sh_m[1];
    float acc0 = expf(slog[(size_t)i*GHH + 0] - m0) * xl[(size_t)i*(GHH*CC) + c];
    float acc1 = expf(slog[(size_t)i*GHH + 1] - m1) * xl[(size_t)i*(GHH*CC) + CC + c];

    __shared__ float s_w0[64], s_w1[64];
    __shared__ int   s_si[64];
    for (int ch = p0; ch < p1; ch += 64) {
        int cn = min(64, p1 - ch);
        if (tid < cn) {
            int e = d_csr_eid[ch + tid];
            s_si[tid] = (g << 7) + edge[e];
            size_t eb = ((size_t)(g << 10) + e) * GHH;
            s_w0[tid] = expf(elog[eb + 0] - m0);
            s_w1[tid] = expf(elog[eb + 1] - m1);
        }
        __syncthreads();
        for (int p = 0; p < cn; p++) {
            size_t sb = (size_t)s_si[p] * (GHH*CC);
            acc0 = fmaf(s_w0[p], xl[sb + c], acc0);
            acc1 = fmaf(s_w1[p], xl[sb + CC + c], acc1);
        }
        __syncthreads();
    }
    float hg = 0.5f * (acc0 / (sh_d[0] + 1e-16f) + acc1 / (sh_d[1] + 1e-16f)) + gatb[c];
    float v = h[(size_t)i*CC + c] + hg;

    __shared__ float sred[256];
    sred[c] = v; __syncthreads();
#pragma unroll
    for (int s = 128; s; s >>= 1) { if (c < s) sred[c] += sred[c + s]; __syncthreads(); }
    float mean = sred[0] * (1.f/256.f); __syncthreads();
    float d = v - mean;
    sred[c] = d * d; __syncthreads();
#pragma unroll
    for (int s = 128; s; s >>= 1) { if (c < s) sred[c] += sred[c + s]; __syncthreads(); }
    float var = sred[0] * (1.f/256.f);
    h[(size_t)i*CC + c] = d * rsqrtf(var + 1e-5f) * gamma[c] + beta[c];
}

// ---------------- MHA over stations (one block per query node) ----------------
__global__ void __launch_bounds__(128) mha_kernel(const float* __restrict__ q,
                                                  const float* __restrict__ k,
                                                  const float* __restrict__ v,
                                                  float* __restrict__ aohead) {
    int i = blockIdx.x;
    int bt = i >> 7;
    int base = bt << 7;
    int tid = threadIdx.x;          // 128
    __shared__ float s_q[64], s_s[128], s_red[8];
    for (int h = 0; h < NHH; h++) {
        int off = h << 6;
        if (tid < 64) s_q[tid] = q[(size_t)i*CC + off + tid];
        __syncthreads();
        const float* krow = k + (size_t)(base + tid) * CC + off;
        float s = 0.f;
#pragma unroll 8
        for (int d = 0; d < 64; d++) s = fmaf(s_q[d], krow[d], s);
        s *= 0.125f;
        float m = s;
#pragma unroll
        for (int o = 16; o; o >>= 1) m = fmaxf(m, __shfl_xor_sync(0xffffffffu, m, o));
        if ((tid & 31) == 0) s_red[tid >> 5] = m;
        __syncthreads();
        float mm = fmaxf(fmaxf(s_red[0], s_red[1]), fmaxf(s_red[2], s_red[3]));
        float e = expf(s - mm);
        float sum = e;
#pragma unroll
        for (int o = 16; o; o >>= 1) sum += __shfl_xor_sync(0xffffffffu, sum, o);
        if ((tid & 31) == 0) s_red[4 + (tid >> 5)] = sum;
        __syncthreads();
        float tot = s_red[4] + s_red[5] + s_red[6] + s_red[7];
        s_s[tid] = e / tot;
        __syncthreads();
        if (tid < 64) {
            float o = 0.f;
#pragma unroll 8
            for (int j = 0; j < 128; j++)
                o = fmaf(s_s[j], v[(size_t)(base + j) * CC + off + tid], o);
            aohead[(size_t)i*CC + off + tid] = o;
        }
        __syncthreads();
    }
}

// ---------------- residual + LayerNorm ----------------
__global__ void __launch_bounds__(256) resid_ln_kernel(const float* __restrict__ hd,
                                                       const float* __restrict__ ao,
                                                       const float* __restrict__ gamma,
                                                       const float* __restrict__ beta,
                                                       float* __restrict__ out) {
    int i = blockIdx.x;
    int c = threadIdx.x;
    float v = hd[(size_t)i*CC + c] + ao[(size_t)i*CC + c];
    __shared__ float sred[256];
    sred[c] = v; __syncthreads();
#pragma unroll
    for (int s = 128; s; s >>= 1) { if (c < s) sred[c] += sred[c + s]; __syncthreads(); }
    float mean = sred[0] * (1.f/256.f); __syncthreads();
    float d = v - mean;
    sred[c] = d * d; __syncthreads();
#pragma unroll
    for (int s = 128; s; s >>= 1) { if (c < s) sred[c] += sred[c + s]; __syncthreads(); }
    float var = sred[0] * (1.f/256.f);
    out[(size_t)i*CC + c] = d * rsqrtf(var + 1e-5f) * gamma[c] + beta[c];
}

// ---------------- gate + skip + output head + softplus ----------------
__global__ void __launch_bounds__(256) final_kernel(const float* __restrict__ gpre,
                                                    const float* __restrict__ href,
                                                    const float* __restrict__ skip2,
                                                    const float* __restrict__ W_out,
                                                    const float* __restrict__ b_out,
                                                    float* __restrict__ out) {
    int i = blockIdx.x;
    int c = threadIdx.x;
    float g = 1.f / (1.f + expf(-gpre[(size_t)i*CC + c]));
    float hf = g * href[(size_t)i*CC + c] + (1.f - g) * skip2[(size_t)i*CC + c];
    __shared__ float r0[256], r1[256];
    r0[c] = hf * W_out[c*2 + 0];
    r1[c] = hf * W_out[c*2 + 1];
    __syncthreads();
#pragma unroll
    for (int s = 128; s; s >>= 1) {
        if (c < s) { r0[c] += r0[c + s]; r1[c] += r1[c + s]; }
        __syncthreads();
    }
    if (c == 0) {
        float o0 = r0[0] + b_out[0];
        float o1 = r1[0] + b_out[1];
        out[(size_t)i*2 + 0] = o0;
        out[(size_t)i*2 + 1] = fmaxf(o1, 0.f) + log1pf(expf(-fabsf(o1)));
    }
}

// ---------------- host orchestration ----------------
extern "C" void kernel_launch(void* const* d_in, const int* in_sizes, int n_in,
                              void* d_out, int out_size) {
    const float* x        = (const float*)d_in[0];
    const int*   edge     = (const int*)  d_in[1];
    const float* W_enc    = (const float*)d_in[2];
    const float* b_enc    = (const float*)d_in[3];
    const float* station  = (const float*)d_in[4];
    const float* horizon  = (const float*)d_in[5];
    const float* conv_w   = (const float*)d_in[6];
    const float* conv_b   = (const float*)d_in[7];
    const float* gat_wl   = (const float*)d_in[8];
    const float* gat_wr   = (const float*)d_in[9];
    const float* gat_att  = (const float*)d_in[10];
    const float* gat_b    = (const float*)d_in[11];
    const float* norm_g   = (const float*)d_in[12];
    const float* norm_b   = (const float*)d_in[13];
    const float* Wq       = (const float*)d_in[14];
    const float* Wk       = (const float*)d_in[15];
    const float* Wv       = (const float*)d_in[16];
    const float* Wo       = (const float*)d_in[17];
    const float* bq       = (const float*)d_in[18];
    const float* bk       = (const float*)d_in[19];
    const float* bv       = (const float*)d_in[20];
    const float* bo       = (const float*)d_in[21];
    const float* an_g     = (const float*)d_in[22];
    const float* an_b     = (const float*)d_in[23];
    const float* W_skip   = (const float*)d_in[24];
    const float* b_skip   = (const float*)d_in[25];
    const float* W_gate   = (const float*)d_in[26];
    const float* b_gate   = (const float*)d_in[27];
    const float* W_out    = (const float*)d_in[28];
    const float* b_out    = (const float*)d_in[29];
    float* out = (float*)d_out;

    float* buf = nullptr;
    cudaGetSymbolAddress((void**)&buf, d_buf);
    float* g_h    = buf + OFF_H;
    float* g_y    = buf + OFF_Y;
    float* g_skip = buf + OFF_SKIP;
    float* g_xl   = buf + OFF_XL;
    float* g_xr   = buf + OFF_XR;
    float* g_q    = buf + OFF_Q;
    float* g_k    = buf + OFF_K;
    float* g_v    = buf + OFF_V;
    float* g_ao   = buf + OFF_AO;
    float* g_href = buf + OFF_HREF;
    float* g_elog = buf + OFF_ELOG;
    float* g_slog = buf + OFF_SLOG;
    float* g_wt   = buf + OFF_WT;

    const dim3 thr(256);
    const dim3 gN256(CC/64, NNODE/64);          // (4, 192)
    const dim3 gN512((GHH*CC)/64, NNODE/64);    // (8, 192)
    const int EW = NNODE;                       // elementwise grid: NNODE*CC / 256

    // CSR of base graph (deterministic)
    build_csr_kernel<<<1, NST>>>(edge);

    // encoder: h = x @ W_enc + b_enc, then + station/horizon embeddings
    gemm_kernel<0><<<gN256, thr>>>(x, W_enc, b_enc, g_h, NNODE, CC, FINF);
    add_emb_kernel<<<EW, thr>>>(g_h, station, horizon);

    for (int l = 0; l < LL; l++) {
        int dil = 1 << l;
        transpose_w_kernel<<<(KK*CC*CC)/256, thr>>>(conv_w + (size_t)l*CC*CC*KK, g_wt);
        conv_gemm_kernel<<<gN256, thr>>>(g_h, g_wt, conv_b + l*CC, g_y, dil);
        add_skip_kernel<<<EW, thr>>>(g_y, g_skip, g_h, l == 0 ? 1 : 0);

        gemm_kernel<0><<<gN512, thr>>>(g_h, gat_wl + (size_t)l*CC*GHH*CC, nullptr, g_xl,
                                       NNODE, GHH*CC, CC);
        gemm_kernel<0><<<gN512, thr>>>(g_h, gat_wr + (size_t)l*CC*GHH*CC, nullptr, g_xr,
                                       NNODE, GHH*CC, CC);
        edge_logits_kernel<<<EBASE + NNODE, 64>>>(g_xl, g_xr, gat_att + l*GHH*CC, edge,
                                                  g_elog, g_slog);
        gat_agg_ln_kernel<<<NNODE, thr>>>(edge, g_xl, g_elog, g_slog,
                                          gat_b + l*CC, norm_g + l*CC, norm_b + l*CC, g_h);
    }

    // h_deep = sum(skips) + h_tcn  -> g_y (hd)
    add2_kernel<<<EW, thr>>>(g_skip, g_h, g_y);

    // global spatial MHA
    gemm_kernel<0><<<gN256, thr>>>(g_y, Wq, bq, g_q, NNODE, CC, CC);
    gemm_kernel<0><<<gN256, thr>>>(g_y, Wk, bk, g_k, NNODE, CC, CC);
    gemm_kernel<0><<<gN256, thr>>>(g_y, Wv, bv, g_v, NNODE, CC, CC);
    mha_kernel<<<NNODE, 128>>>(g_q, g_k, g_v, g_xl);                 // g_xl = ao heads
    gemm_kernel<0><<<gN256, thr>>>(g_xl, Wo, bo, g_ao, NNODE, CC, CC);
    resid_ln_kernel<<<NNODE, thr>>>(g_y, g_ao, an_g, an_b, g_href);

    // gate + skip branch + output head
    gemm_kernel<0><<<gN256, thr>>>(x, W_skip, b_skip, g_skip, NNODE, CC, FINF);
    gemm_kernel<0><<<gN256, thr>>>(g_href, W_gate, b_gate, g_xr, NNODE, CC, CC);
    final_kernel<<<NNODE, thr>>>(g_xr, g_href, g_skip, W_out, b_out, out);

    (void)in_sizes; (void)n_in; (void)out_size;
}

// round 2
// speedup vs baseline: 1.0874x; 1.0874x over previous
#include <cuda_runtime.h>
#include <math.h>
#include <stdint.h>

// ---------------- problem constants ----------------
#define BBATCH 4
#define TT     24
#define NST    128
#define FINF   64
#define CC     256
#define LL     3
#define KK     3
#define GHH    2
#define NHH    4
#define EE     1024
#define NG     (BBATCH*TT)        // 96 graphs
#define NNODE  (NG*NST)           // 12288 nodes

// ---------------- static scratch ----------------
__device__ int d_csr_ptr[NST+1];
__device__ int d_csr_eid[EE];

#define OFF_H    ((size_t)0)
#define OFF_Y    (OFF_H    + (size_t)NNODE*CC)
#define OFF_SKIP (OFF_Y    + (size_t)NNODE*CC)
#define OFF_XL   (OFF_SKIP + (size_t)NNODE*CC)
#define OFF_XR   (OFF_XL   + (size_t)NNODE*GHH*CC)
#define OFF_Q    (OFF_XR   + (size_t)NNODE*GHH*CC)
#define OFF_K    (OFF_Q    + (size_t)NNODE*CC)
#define OFF_V    (OFF_K    + (size_t)NNODE*CC)
#define OFF_AO   (OFF_V    + (size_t)NNODE*CC)
#define OFF_HREF (OFF_AO   + (size_t)NNODE*CC)
#define OFF_WT   (OFF_HREF + (size_t)NNODE*CC)
#define TOTF     (OFF_WT   + (size_t)LL*KK*CC*CC)
__device__ float d_buf[TOTF];

// ---------------- helpers ----------------
__device__ __forceinline__ float tf32r(float x) {
    uint32_t u;
    asm("cvt.rna.tf32.f32 %0, %1;" : "=r"(u) : "f"(x));
    return __uint_as_float(u);
}
#define U32F(f) __float_as_uint(f)

__device__ __forceinline__ void mma8(float4& d, const uint32_t a[4],
                                     uint32_t b0, uint32_t b1) {
    asm volatile(
        "mma.sync.aligned.m16n8k8.row.col.f32.tf32.tf32.f32 "
        "{%0,%1,%2,%3},{%4,%5,%6,%7},{%8,%9},{%0,%1,%2,%3};"
        : "+f"(d.x), "+f"(d.y), "+f"(d.z), "+f"(d.w)
        : "r"(a[0]), "r"(a[1]), "r"(a[2]), "r"(a[3]), "r"(b0), "r"(b1));
}

// ---------------- deterministic CSR of base graph ----------------
__global__ void build_csr_kernel(const int* __restrict__ edge) {
    const int* dst = edge + EE;
    int n = threadIdx.x;             // 0..127
    __shared__ int counts[NST];
    int cnt = 0;
    for (int e = 0; e < EE; e++) if (dst[e] == n) cnt++;
    counts[n] = cnt;
    __syncthreads();
    if (n == 0) {
        int s = 0;
        for (int i = 0; i < NST; i++) { d_csr_ptr[i] = s; s += counts[i]; }
        d_csr_ptr[NST] = s;
    }
    __syncthreads();
    int p = d_csr_ptr[n];
    for (int e = 0; e < EE; e++) if (dst[e] == n) d_csr_eid[p++] = e;  // stable
}

// ---------------- tf32 tensor-core GEMM, 3xTF32 split ----------------
// BM=128 BN=128 BK=16, 256 threads, warp grid 4x2, warp tile 32x64.
// EPI: 0 = (+bias), 1 = +bias+station+horizon, 2 = relu(+bias)
// CONV: gathered A for dilated causal conv (Kd = 3*256)
template<int EPI, int CONV>
__global__ void __launch_bounds__(256) gemm_tc(
    const float* __restrict__ A, const float* __restrict__ B,
    const float* __restrict__ bias, float* __restrict__ C,
    int M, int N, int Kd, int dil,
    const float* __restrict__ aux1, const float* __restrict__ aux2)
{
    __shared__ float As_hi[16][132], As_lo[16][132];
    __shared__ float Bs_hi[16][132], Bs_lo[16][132];

    int tid = threadIdx.x, lane = tid & 31, w = tid >> 5;
    int bm = blockIdx.y << 7, bn = blockIdx.x << 7;
    int wm = w >> 1, wn = w & 1;
    int r = lane >> 2, cg = lane & 3;

    float4 acc[2][8];
#pragma unroll
    for (int mt = 0; mt < 2; mt++)
#pragma unroll
        for (int nt = 0; nt < 8; nt++) acc[mt][nt] = make_float4(0.f, 0.f, 0.f, 0.f);

    int am = tid >> 2;                 // 0..63
    int ak = (tid & 3) << 2;           // 0,4,8,12

    for (int k0 = 0; k0 < Kd; k0 += 16) {
        __syncthreads();
        // ---- stage A (hi/lo split) ----
#pragma unroll
        for (int i = 0; i < 2; i++) {
            int m = am + (i << 6);
            float4 v;
            if (CONV) {
                int kg = k0 + ak;
                int tap = kg >> 8;
                int shift = (2 - tap) * dil;
                int node = bm + m;
                int t = (node >> 7) % TT;
                if (t >= shift)
                    v = *(const float4*)(A + (size_t)(node - (shift << 7)) * CC + (kg & 255));
                else
                    v = make_float4(0.f, 0.f, 0.f, 0.f);
            } else {
                v = *(const float4*)(A + (size_t)(bm + m) * Kd + k0 + ak);
            }
            float h0 = tf32r(v.x), h1 = tf32r(v.y), h2 = tf32r(v.z), h3 = tf32r(v.w);
            As_hi[ak+0][m] = h0; As_hi[ak+1][m] = h1;
            As_hi[ak+2][m] = h2; As_hi[ak+3][m] = h3;
            As_lo[ak+0][m] = tf32r(v.x - h0); As_lo[ak+1][m] = tf32r(v.y - h1);
            As_lo[ak+2][m] = tf32r(v.z - h2); As_lo[ak+3][m] = tf32r(v.w - h3);
        }
        // ---- stage B ----
#pragma unroll
        for (int i = 0; i < 2; i++) {
            int lin = tid + (i << 8);
            int kr = lin >> 5;
            int nc = (lin & 31) << 2;
            float4 v = *(const float4*)(B + (size_t)(k0 + kr) * N + bn + nc);
            float4 hi, lo;
            hi.x = tf32r(v.x); hi.y = tf32r(v.y); hi.z = tf32r(v.z); hi.w = tf32r(v.w);
            lo.x = tf32r(v.x - hi.x); lo.y = tf32r(v.y - hi.y);
            lo.z = tf32r(v.z - hi.z); lo.w = tf32r(v.w - hi.w);
            *(float4*)&Bs_hi[kr][nc] = hi;
            *(float4*)&Bs_lo[kr][nc] = lo;
        }
        __syncthreads();
        // ---- compute: two k8 steps ----
#pragma unroll
        for (int kk = 0; kk < 16; kk += 8) {
            uint32_t ah[2][4], al[2][4];
#pragma unroll
            for (int mt = 0; mt < 2; mt++) {
                int m = (wm << 5) + (mt << 4) + r;
                ah[mt][0] = U32F(As_hi[kk+cg  ][m]);   ah[mt][1] = U32F(As_hi[kk+cg  ][m+8]);
                ah[mt][2] = U32F(As_hi[kk+cg+4][m]);   ah[mt][3] = U32F(As_hi[kk+cg+4][m+8]);
                al[mt][0] = U32F(As_lo[kk+cg  ][m]);   al[mt][1] = U32F(As_lo[kk+cg  ][m+8]);
                al[mt][2] = U32F(As_lo[kk+cg+4][m]);   al[mt][3] = U32F(As_lo[kk+cg+4][m+8]);
            }
#pragma unroll
            for (int nt = 0; nt < 8; nt++) {
                int n = (wn << 6) + (nt << 3) + r;
                uint32_t bh0 = U32F(Bs_hi[kk+cg  ][n]);
                uint32_t bh1 = U32F(Bs_hi[kk+cg+4][n]);
                uint32_t bl0 = U32F(Bs_lo[kk+cg  ][n]);
                uint32_t bl1 = U32F(Bs_lo[kk+cg+4][n]);
#pragma unroll
                for (int mt = 0; mt < 2; mt++) {
                    mma8(acc[mt][nt], ah[mt], bh0, bh1);
                    mma8(acc[mt][nt], ah[mt], bl0, bl1);
                    mma8(acc[mt][nt], al[mt], bh0, bh1);
                }
            }
        }
    }

    // ---- epilogue ----
#pragma unroll
    for (int mt = 0; mt < 2; mt++) {
        int m0 = bm + (wm << 5) + (mt << 4) + r;
        int m1 = m0 + 8;
#pragma unroll
        for (int nt = 0; nt < 8; nt++) {
            int col = bn + (wn << 6) + (nt << 3) + (cg << 1);
            float b0 = bias ? bias[col] : 0.f;
            float b1 = bias ? bias[col+1] : 0.f;
            float2 v0 = make_float2(acc[mt][nt].x + b0, acc[mt][nt].y + b1);
            float2 v1 = make_float2(acc[mt][nt].z + b0, acc[mt][nt].w + b1);
            if (EPI == 1) {
                int s0 = (m0 & 127) * CC + col, t0 = ((m0 >> 7) % TT) * CC + col;
                int s1 = (m1 & 127) * CC + col, t1 = ((m1 >> 7) % TT) * CC + col;
                v0.x += aux1[s0] + aux2[t0];     v0.y += aux1[s0+1] + aux2[t0+1];
                v1.x += aux1[s1] + aux2[t1];     v1.y += aux1[s1+1] + aux2[t1+1];
            }
            if (EPI == 2) {
                v0.x = fmaxf(v0.x, 0.f); v0.y = fmaxf(v0.y, 0.f);
                v1.x = fmaxf(v1.x, 0.f); v1.y = fmaxf(v1.y, 0.f);
            }
            *(float2*)(C + (size_t)m0 * N + col) = v0;
            *(float2*)(C + (size_t)m1 * N + col) = v1;
        }
    }
}

// ---------------- conv weight transpose, all layers ----------------
__global__ void transpose_w_all(const float* __restrict__ w, float* __restrict__ wt) {
    int idx = blockIdx.x * 256 + threadIdx.x;        // < 3*3*256*256
    int l = idx / (KK*CC*CC);
    int rem = idx - l * (KK*CC*CC);
    int tap = rem >> 16;
    int cin = (rem >> 8) & 255;
    int cout = rem & 255;
    wt[idx] = w[(((size_t)l*CC + cout)*CC + cin)*KK + tap];
}

// ---------------- small elementwise kernels ----------------
__global__ void add_skip_kernel(const float* __restrict__ y,
                                float* __restrict__ skip, float* __restrict__ h, int first) {
    int idx = blockIdx.x * 256 + threadIdx.x;
    float v = y[idx];
    skip[idx] = (first ? 0.f : skip[idx]) + v;
    h[idx] += v;
}

__global__ void add2_kernel(const float* __restrict__ a, const float* __restrict__ b,
                            float* __restrict__ o) {
    int idx = blockIdx.x * 256 + threadIdx.x;
    o[idx] = a[idx] + b[idx];
}

// ---------------- fused GAT: logits + softmax + aggregate + residual + LN ------
__global__ void __launch_bounds__(256) gat_fused_kernel(
    const int* __restrict__ edge, const float* __restrict__ xl,
    const float* __restrict__ xr, const float* __restrict__ att,
    const float* __restrict__ gatb, const float* __restrict__ gamma,
    const float* __restrict__ beta, float* __restrict__ h)
{
    int i = blockIdx.x;
    int tid = threadIdx.x, lane = tid & 31, w = tid >> 5;
    int g = i >> 7, n = i & 127;
    int p0 = d_csr_ptr[n], p1 = d_csr_ptr[n+1];
    int nE = p1 - p0 + 1;     // + self loop (j=0)

    __shared__ float xr_sh[512], att_sh[512];
    __shared__ float2 logit_sh[EE + 1];
    __shared__ float sh_m[2], sh_d[2];
    __shared__ float s_w0[64], s_w1[64];
    __shared__ int   s_si[64];

    xr_sh[tid]       = xr[(size_t)i*512 + tid];
    xr_sh[256 + tid] = xr[(size_t)i*512 + 256 + tid];
    att_sh[tid]       = att[tid];
    att_sh[256 + tid] = att[256 + tid];
    __syncthreads();

    // phase A: per-edge logits (warp per edge)
    for (int j = w; j < nE; j += 8) {
        int src = (j == 0) ? i : ((g << 7) + edge[d_csr_eid[p0 + j - 1]]);
        const float* px = xl + (size_t)src * 512;
        float s0 = 0.f, s1 = 0.f;
        for (int c = lane; c < 256; c += 32) {
            float v0 = px[c] + xr_sh[c];
            v0 = v0 > 0.f ? v0 : 0.2f * v0;
            s0 = fmaf(att_sh[c], v0, s0);
            float v1 = px[256 + c] + xr_sh[256 + c];
            v1 = v1 > 0.f ? v1 : 0.2f * v1;
            s1 = fmaf(att_sh[256 + c], v1, s1);
        }
#pragma unroll
        for (int o = 16; o; o >>= 1) {
            s0 += __shfl_xor_sync(0xffffffffu, s0, o);
            s1 += __shfl_xor_sync(0xffffffffu, s1, o);
        }
        if (lane == 0) logit_sh[j] = make_float2(s0, s1);
    }
    __syncthreads();

    // phase B: per-head max + denominator (warp per head)
    if (w < 2) {
        float m = -1e30f;
        for (int j = lane; j < nE; j += 32) {
            float lv = (w == 0) ? logit_sh[j].x : logit_sh[j].y;
            m = fmaxf(m, lv);
        }
#pragma unroll
        for (int o = 16; o; o >>= 1) m = fmaxf(m, __shfl_xor_sync(0xffffffffu, m, o));
        float den = 0.f;
        for (int j = lane; j < nE; j += 32) {
            float lv = (w == 0) ? logit_sh[j].x : logit_sh[j].y;
            den += expf(lv - m);
        }
#pragma unroll
        for (int o = 16; o; o >>= 1) den += __shfl_xor_sync(0xffffffffu, den, o);
        if (lane == 0) { sh_m[w] = m; sh_d[w] = den; }
    }
    __syncthreads();

    // phase C: weighted aggregation
    float m0 = sh_m[0], m1 = sh_m[1];
    int c = tid;
    float acc0 = 0.f, acc1 = 0.f;
    for (int ch = 0; ch < nE; ch += 64) {
        int cn = min(64, nE - ch);
        if (tid < cn) {
            int j = ch + tid;
            s_si[tid] = (j == 0) ? i : ((g << 7) + edge[d_csr_eid[p0 + j - 1]]);
            s_w0[tid] = expf(logit_sh[j].x - m0);
            s_w1[tid] = expf(logit_sh[j].y - m1);
        }
        __syncthreads();
        for (int p = 0; p < cn; p++) {
            size_t sb = (size_t)s_si[p] * 512;
            acc0 = fmaf(s_w0[p], xl[sb + c], acc0);
            acc1 = fmaf(s_w1[p], xl[sb + 256 + c], acc1);
        }
        __syncthreads();
    }
    float hg = 0.5f * (acc0 / (sh_d[0] + 1e-16f) + acc1 / (sh_d[1] + 1e-16f)) + gatb[c];
    float v = h[(size_t)i*CC + c] + hg;

    // residual + LayerNorm (reuse att_sh as reduction buffer)
    float* sred = att_sh;
    sred[c] = v; __syncthreads();
#pragma unroll
    for (int s = 128; s; s >>= 1) { if (c < s) sred[c] += sred[c + s]; __syncthreads(); }
    float mean = sred[0] * (1.f/256.f); __syncthreads();
    float d = v - mean;
    sred[c] = d * d; __syncthreads();
#pragma unroll
    for (int s = 128; s; s >>= 1) { if (c < s) sred[c] += sred[c + s]; __syncthreads(); }
    float var = sred[0] * (1.f/256.f);
    h[(size_t)i*CC + c] = d * rsqrtf(var + 1e-5f) * gamma[c] + beta[c];
}

// ---------------- MHA over stations (one block per query node) ----------------
__global__ void __launch_bounds__(128) mha_kernel(const float* __restrict__ q,
                                                  const float* __restrict__ k,
                                                  const float* __restrict__ v,
                                                  float* __restrict__ aohead) {
    int i = blockIdx.x;
    int base = (i >> 7) << 7;
    int tid = threadIdx.x;          // 128
    __shared__ float s_q[64], s_s[128], s_red[8];
    for (int h = 0; h < NHH; h++) {
        int off = h << 6;
        if (tid < 64) s_q[tid] = q[(size_t)i*CC + off + tid];
        __syncthreads();
        const float* krow = k + (size_t)(base + tid) * CC + off;
        float s = 0.f;
#pragma unroll 8
        for (int d = 0; d < 64; d++) s = fmaf(s_q[d], krow[d], s);
        s *= 0.125f;
        float m = s;
#pragma unroll
        for (int o = 16; o; o >>= 1) m = fmaxf(m, __shfl_xor_sync(0xffffffffu, m, o));
        if ((tid & 31) == 0) s_red[tid >> 5] = m;
        __syncthreads();
        float mm = fmaxf(fmaxf(s_red[0], s_red[1]), fmaxf(s_red[2], s_red[3]));
        float e = expf(s - mm);
        float sum = e;
#pragma unroll
        for (int o = 16; o; o >>= 1) sum += __shfl_xor_sync(0xffffffffu, sum, o);
        if ((tid & 31) == 0) s_red[4 + (tid >> 5)] = sum;
        __syncthreads();
        float tot = s_red[4] + s_red[5] + s_red[6] + s_red[7];
        s_s[tid] = e / tot;
        __syncthreads();
        if (tid < 64) {
            float o = 0.f;
#pragma unroll 8
            for (int j = 0; j < 128; j++)
                o = fmaf(s_s[j], v[(size_t)(base + j) * CC + off + tid], o);
            aohead[(size_t)i*CC + off + tid] = o;
        }
        __syncthreads();
    }
}

// ---------------- residual + LayerNorm ----------------
__global__ void __launch_bounds__(256) resid_ln_kernel(const float* __restrict__ hd,
                                                       const float* __restrict__ ao,
                                                       const float* __restrict__ gamma,
                                                       const float* __restrict__ beta,
                                                       float* __restrict__ out) {
    int i = blockIdx.x;
    int c = threadIdx.x;
    float v = hd[(size_t)i*CC + c] + ao[(size_t)i*CC + c];
    __shared__ float sred[256];
    sred[c] = v; __syncthreads();
#pragma unroll
    for (int s = 128; s; s >>= 1) { if (c < s) sred[c] += sred[c + s]; __syncthreads(); }
    float mean = sred[0] * (1.f/256.f); __syncthreads();
    float d = v - mean;
    sred[c] = d * d; __syncthreads();
#pragma unroll
    for (int s = 128; s; s >>= 1) { if (c < s) sred[c] += sred[c + s]; __syncthreads(); }
    float var = sred[0] * (1.f/256.f);
    out[(size_t)i*CC + c] = d * rsqrtf(var + 1e-5f) * gamma[c] + beta[c];
}

// ---------------- gate + skip + output head + softplus ----------------
__global__ void __launch_bounds__(256) final_kernel(const float* __restrict__ gpre,
                                                    const float* __restrict__ href,
                                                    const float* __restrict__ skip2,
                                                    const float* __restrict__ W_out,
                                                    const float* __restrict__ b_out,
                                                    float* __restrict__ out) {
    int i = blockIdx.x;
    int c = threadIdx.x;
    float g = 1.f / (1.f + expf(-gpre[(size_t)i*CC + c]));
    float hf = g * href[(size_t)i*CC + c] + (1.f - g) * skip2[(size_t)i*CC + c];
    __shared__ float r0[256], r1[256];
    r0[c] = hf * W_out[c*2 + 0];
    r1[c] = hf * W_out[c*2 + 1];
    __syncthreads();
#pragma unroll
    for (int s = 128; s; s >>= 1) {
        if (c < s) { r0[c] += r0[c + s]; r1[c] += r1[c + s]; }
        __syncthreads();
    }
    if (c == 0) {
        float o0 = r0[0] + b_out[0];
        float o1 = r1[0] + b_out[1];
        out[(size_t)i*2 + 0] = o0;
        out[(size_t)i*2 + 1] = fmaxf(o1, 0.f) + log1pf(expf(-fabsf(o1)));
    }
}

// ---------------- host orchestration ----------------
extern "C" void kernel_launch(void* const* d_in, const int* in_sizes, int n_in,
                              void* d_out, int out_size) {
    const float* x        = (const float*)d_in[0];
    const int*   edge     = (const int*)  d_in[1];
    const float* W_enc    = (const float*)d_in[2];
    const float* b_enc    = (const float*)d_in[3];
    const float* station  = (const float*)d_in[4];
    const float* horizon  = (const float*)d_in[5];
    const float* conv_w   = (const float*)d_in[6];
    const float* conv_b   = (const float*)d_in[7];
    const float* gat_wl   = (const float*)d_in[8];
    const float* gat_wr   = (const float*)d_in[9];
    const float* gat_att  = (const float*)d_in[10];
    const float* gat_b    = (const float*)d_in[11];
    const float* norm_g   = (const float*)d_in[12];
    const float* norm_b   = (const float*)d_in[13];
    const float* Wq       = (const float*)d_in[14];
    const float* Wk       = (const float*)d_in[15];
    const float* Wv       = (const float*)d_in[16];
    const float* Wo       = (const float*)d_in[17];
    const float* bq       = (const float*)d_in[18];
    const float* bk       = (const float*)d_in[19];
    const float* bv       = (const float*)d_in[20];
    const float* bo       = (const float*)d_in[21];
    const float* an_g     = (const float*)d_in[22];
    const float* an_b     = (const float*)d_in[23];
    const float* W_skip   = (const float*)d_in[24];
    const float* b_skip   = (const float*)d_in[25];
    const float* W_gate   = (const float*)d_in[26];
    const float* b_gate   = (const float*)d_in[27];
    const float* W_out    = (const float*)d_in[28];
    const float* b_out    = (const float*)d_in[29];
    float* out = (float*)d_out;

    float* buf = nullptr;
    cudaGetSymbolAddress((void**)&buf, d_buf);
    float* g_h    = buf + OFF_H;
    float* g_y    = buf + OFF_Y;
    float* g_skip = buf + OFF_SKIP;
    float* g_xl   = buf + OFF_XL;
    float* g_xr   = buf + OFF_XR;
    float* g_q    = buf + OFF_Q;
    float* g_k    = buf + OFF_K;
    float* g_v    = buf + OFF_V;
    float* g_ao   = buf + OFF_AO;
    float* g_href = buf + OFF_HREF;
    float* g_wt   = buf + OFF_WT;

    const dim3 thr(256);
    const dim3 gN256(CC/128, NNODE/128);          // (2, 96)
    const dim3 gN512((GHH*CC)/128, NNODE/128);    // (4, 96)
    const int EW = NNODE;                          // elementwise grid

    build_csr_kernel<<<1, NST>>>(edge);
    transpose_w_all<<<(LL*KK*CC*CC)/256, thr>>>(conv_w, g_wt);

    // encoder: h = x @ W_enc + b_enc + station + horizon
    gemm_tc<1,0><<<gN256, thr>>>(x, W_enc, b_enc, g_h, NNODE, CC, FINF, 0,
                                 station, horizon);

    for (int l = 0; l < LL; l++) {
        int dil = 1 << l;
        gemm_tc<2,1><<<gN256, thr>>>(g_h, g_wt + (size_t)l*KK*CC*CC, conv_b + l*CC,
                                     g_y, NNODE, CC, KK*CC, dil, nullptr, nullptr);
        add_skip_kernel<<<EW, thr>>>(g_y, g_skip, g_h, l == 0 ? 1 : 0);

        gemm_tc<0,0><<<gN512, thr>>>(g_h, gat_wl + (size_t)l*CC*GHH*CC, nullptr, g_xl,
                                     NNODE, GHH*CC, CC, 0, nullptr, nullptr);
        gemm_tc<0,0><<<gN512, thr>>>(g_h, gat_wr + (size_t)l*CC*GHH*CC, nullptr, g_xr,
                                     NNODE, GHH*CC, CC, 0, nullptr, nullptr);
        gat_fused_kernel<<<NNODE, thr>>>(edge, g_xl, g_xr, gat_att + l*GHH*CC,
                                         gat_b + l*CC, norm_g + l*CC, norm_b + l*CC, g_h);
    }

    // h_deep = sum(skips) + h_tcn
    add2_kernel<<<EW, thr>>>(g_skip, g_h, g_y);

    // global spatial MHA
    gemm_tc<0,0><<<gN256, thr>>>(g_y, Wq, bq, g_q, NNODE, CC, CC, 0, nullptr, nullptr);
    gemm_tc<0,0><<<gN256, thr>>>(g_y, Wk, bk, g_k, NNODE, CC, CC, 0, nullptr, nullptr);
    gemm_tc<0,0><<<gN256, thr>>>(g_y, Wv, bv, g_v, NNODE, CC, CC, 0, nullptr, nullptr);
    mha_kernel<<<NNODE, 128>>>(g_q, g_k, g_v, g_xl);
    gemm_tc<0,0><<<gN256, thr>>>(g_xl, Wo, bo, g_ao, NNODE, CC, CC, 0, nullptr, nullptr);
    resid_ln_kernel<<<NNODE, thr>>>(g_y, g_ao, an_g, an_b, g_href);

    // gate + skip branch + output head
    gemm_tc<0,0><<<gN256, thr>>>(x, W_skip, b_skip, g_skip, NNODE, CC, FINF, 0,
                                 nullptr, nullptr);
    gemm_tc<0,0><<<gN256, thr>>>(g_href, W_gate, b_gate, g_xr, NNODE, CC, CC, 0,
                                 nullptr, nullptr);
    final_kernel<<<NNODE, thr>>>(g_xr, g_href, g_skip, W_out, b_out, out);

    (void)in_sizes; (void)n_in; (void)out_size;
}

// round 3
// speedup vs baseline: 2.6756x; 2.4604x over previous
#include <cuda_runtime.h>
#include <math.h>
#include <stdint.h>

// ---------------- problem constants ----------------
#define BBATCH 4
#define TT     24
#define NST    128
#define FINF   64
#define CC     256
#define LL     3
#define KK     3
#define GHH    2
#define NHH    4
#define EE     1024
#define NG     (BBATCH*TT)        // 96
#define NNODE  (NG*NST)           // 12288

// ---------------- static scratch ----------------
__device__ int d_csr_ptr[NST+1];
__device__ int d_csr_eid[EE];

#define OFF_H    ((size_t)0)
#define OFF_SKIP (OFF_H    + (size_t)NNODE*CC)
#define OFF_Y    (OFF_SKIP + (size_t)NNODE*CC)
#define OFF_XLR  (OFF_Y    + (size_t)NNODE*CC)
#define OFF_QKV  (OFF_XLR  + (size_t)NNODE*1024)
#define OFF_AO   (OFF_QKV  + (size_t)NNODE*768)
#define OFF_HREF (OFF_AO   + (size_t)NNODE*CC)
#define OFF_WT   (OFF_HREF + (size_t)NNODE*CC)
#define OFF_WQKV (OFF_WT   + (size_t)LL*KK*CC*CC)
#define OFF_BQKV (OFF_WQKV + (size_t)CC*768)
#define OFF_WLR  (OFF_BQKV + (size_t)768)
#define TOTF     (OFF_WLR  + (size_t)LL*CC*1024)
__device__ float d_buf[TOTF];

// ---------------- helpers ----------------
__device__ __forceinline__ float tf32r(float x) {
    uint32_t u;
    asm("cvt.rna.tf32.f32 %0, %1;" : "=r"(u) : "f"(x));
    return __uint_as_float(u);
}
#define U32F(f) __float_as_uint(f)

__device__ __forceinline__ void mma8(float4& d, const uint32_t a[4],
                                     uint32_t b0, uint32_t b1) {
    asm volatile(
        "mma.sync.aligned.m16n8k8.row.col.f32.tf32.tf32.f32 "
        "{%0,%1,%2,%3},{%4,%5,%6,%7},{%8,%9},{%0,%1,%2,%3};"
        : "+f"(d.x), "+f"(d.y), "+f"(d.z), "+f"(d.w)
        : "r"(a[0]), "r"(a[1]), "r"(a[2]), "r"(a[3]), "r"(b0), "r"(b1));
}

// ---------------- deterministic CSR of base graph ----------------
__global__ void build_csr_kernel(const int* __restrict__ edge) {
    const int* dst = edge + EE;
    int n = threadIdx.x;             // 0..127
    __shared__ int counts[NST];
    int cnt = 0;
    for (int e = 0; e < EE; e++) if (dst[e] == n) cnt++;
    counts[n] = cnt;
    __syncthreads();
    if (n == 0) {
        int s = 0;
        for (int i = 0; i < NST; i++) { d_csr_ptr[i] = s; s += counts[i]; }
        d_csr_ptr[NST] = s;
    }
    __syncthreads();
    int p = d_csr_ptr[n];
    for (int e = 0; e < EE; e++) if (dst[e] == n) d_csr_eid[p++] = e;  // stable
}

// ---------------- tf32 GEMM: BM=128 BN=64 BK=16, 2-term split (B hi/lo) -------
// EPI: 0 = +bias, 1 = +bias+station+horizon (encoder), 2 = relu(+bias)
// AMODE: 0 = plain A, 1 = conv gather (dil), 2 = A + A2
template<int EPI, int AMODE>
__global__ void __launch_bounds__(256, 3) gemm_tc(
    const float* __restrict__ A, const float* __restrict__ A2,
    const float* __restrict__ B, const float* __restrict__ bias,
    float* __restrict__ C, int N, int Kd, int dil,
    const float* __restrict__ aux1, const float* __restrict__ aux2)
{
    __shared__ float  As[16][136];
    __shared__ float2 Bs[16][68];

    int tid = threadIdx.x, lane = tid & 31, w = tid >> 5;
    int bm = blockIdx.y << 7, bn = blockIdx.x << 6;
    int wm = w >> 1, wn = w & 1;         // 4x2 warp grid, warp tile 32x32
    int r = lane >> 2, cg = lane & 3;

    float4 acc[2][4];
#pragma unroll
    for (int mt = 0; mt < 2; mt++)
#pragma unroll
        for (int nt = 0; nt < 4; nt++) acc[mt][nt] = make_float4(0.f, 0.f, 0.f, 0.f);

    int arow = tid >> 2, akq = (tid & 3) << 2;
    int bkr = tid >> 4, bnq = (tid & 15) << 2;

    for (int k0 = 0; k0 < Kd; k0 += 16) {
        __syncthreads();
        // ---- stage A (single tf32) ----
#pragma unroll
        for (int i = 0; i < 2; i++) {
            int m = arow + (i << 6);
            float4 v;
            if (AMODE == 1) {
                int kg = k0 + akq;
                int tap = kg >> 8;
                int shift = (2 - tap) * dil;
                int node = bm + m;
                int t = (node >> 7) % TT;
                if (t >= shift)
                    v = *(const float4*)(A + (size_t)(node - (shift << 7)) * CC + (kg & 255));
                else
                    v = make_float4(0.f, 0.f, 0.f, 0.f);
            } else if (AMODE == 2) {
                size_t off = (size_t)(bm + m) * Kd + k0 + akq;
                float4 a = *(const float4*)(A + off);
                float4 b = *(const float4*)(A2 + off);
                v = make_float4(a.x + b.x, a.y + b.y, a.z + b.z, a.w + b.w);
            } else {
                v = *(const float4*)(A + (size_t)(bm + m) * Kd + k0 + akq);
            }
            As[akq+0][m] = tf32r(v.x); As[akq+1][m] = tf32r(v.y);
            As[akq+2][m] = tf32r(v.z); As[akq+3][m] = tf32r(v.w);
        }
        // ---- stage B (hi/lo float2 pairs) ----
        {
            float4 v = *(const float4*)(B + (size_t)(k0 + bkr) * N + bn + bnq);
            float hx = tf32r(v.x), hy = tf32r(v.y), hz = tf32r(v.z), hw = tf32r(v.w);
            Bs[bkr][bnq+0] = make_float2(hx, tf32r(v.x - hx));
            Bs[bkr][bnq+1] = make_float2(hy, tf32r(v.y - hy));
            Bs[bkr][bnq+2] = make_float2(hz, tf32r(v.z - hz));
            Bs[bkr][bnq+3] = make_float2(hw, tf32r(v.w - hw));
        }
        __syncthreads();
        // ---- compute: two k8 steps ----
#pragma unroll
        for (int kk = 0; kk < 16; kk += 8) {
            uint32_t ah[2][4];
#pragma unroll
            for (int mt = 0; mt < 2; mt++) {
                int m = (wm << 5) + (mt << 4) + r;
                ah[mt][0] = U32F(As[kk+cg  ][m]);
                ah[mt][1] = U32F(As[kk+cg  ][m+8]);
                ah[mt][2] = U32F(As[kk+cg+4][m]);
                ah[mt][3] = U32F(As[kk+cg+4][m+8]);
            }
#pragma unroll
            for (int nt = 0; nt < 4; nt++) {
                int n = (wn << 5) + (nt << 3) + r;
                float2 b0 = Bs[kk+cg  ][n];
                float2 b1 = Bs[kk+cg+4][n];
#pragma unroll
                for (int mt = 0; mt < 2; mt++) {
                    mma8(acc[mt][nt], ah[mt], U32F(b0.x), U32F(b1.x));
                    mma8(acc[mt][nt], ah[mt], U32F(b0.y), U32F(b1.y));
                }
            }
        }
    }

    // ---- epilogue ----
#pragma unroll
    for (int mt = 0; mt < 2; mt++) {
        int m0 = bm + (wm << 5) + (mt << 4) + r;
        int m1 = m0 + 8;
#pragma unroll
        for (int nt = 0; nt < 4; nt++) {
            int col = bn + (wn << 5) + (nt << 3) + (cg << 1);
            float b0 = bias ? bias[col] : 0.f;
            float b1 = bias ? bias[col+1] : 0.f;
            float2 v0 = make_float2(acc[mt][nt].x + b0, acc[mt][nt].y + b1);
            float2 v1 = make_float2(acc[mt][nt].z + b0, acc[mt][nt].w + b1);
            if (EPI == 1) {
                int s0 = (m0 & 127) * CC + col, t0 = ((m0 >> 7) % TT) * CC + col;
                int s1 = (m1 & 127) * CC + col, t1 = ((m1 >> 7) % TT) * CC + col;
                v0.x += aux1[s0] + aux2[t0];     v0.y += aux1[s0+1] + aux2[t0+1];
                v1.x += aux1[s1] + aux2[t1];     v1.y += aux1[s1+1] + aux2[t1+1];
            }
            if (EPI == 2) {
                v0.x = fmaxf(v0.x, 0.f); v0.y = fmaxf(v0.y, 0.f);
                v1.x = fmaxf(v1.x, 0.f); v1.y = fmaxf(v1.y, 0.f);
            }
            *(float2*)(C + (size_t)m0 * N + col) = v0;
            *(float2*)(C + (size_t)m1 * N + col) = v1;
        }
    }
}

// ---------------- weight prep ----------------
__global__ void transpose_w_all(const float* __restrict__ w, float* __restrict__ wt) {
    int idx = blockIdx.x * 256 + threadIdx.x;        // < 3*3*256*256
    int l = idx / (KK*CC*CC);
    int rem = idx - l * (KK*CC*CC);
    int tap = rem >> 16;
    int cin = (rem >> 8) & 255;
    int cout = rem & 255;
    wt[idx] = w[(((size_t)l*CC + cout)*CC + cin)*KK + tap];
}

__global__ void pack_qkv_kernel(const float* __restrict__ Wq, const float* __restrict__ Wk,
                                const float* __restrict__ Wv, const float* __restrict__ bq,
                                const float* __restrict__ bk, const float* __restrict__ bv,
                                float* __restrict__ W, float* __restrict__ b) {
    int idx = blockIdx.x * 256 + threadIdx.x;        // < 256*768
    int k = idx / 768, n = idx - k * 768;
    int sel = n >> 8, nn = n & 255;
    const float* src = sel == 0 ? Wq : (sel == 1 ? Wk : Wv);
    W[idx] = src[k * CC + nn];
    if (idx < 768) {
        const float* bs = sel == 0 ? bq : (sel == 1 ? bk : bv);
        b[idx] = bs[nn];
    }
}

__global__ void pack_wlr_kernel(const float* __restrict__ wl, const float* __restrict__ wr,
                                float* __restrict__ W) {
    int idx = blockIdx.x * 256 + threadIdx.x;        // < 3*256*1024
    int l = idx >> 18;
    int rem = idx & 262143;
    int k = rem >> 10, n = rem & 1023;
    W[idx] = (n < 512) ? wl[(size_t)l*CC*512 + k*512 + n]
                       : wr[(size_t)l*CC*512 + k*512 + (n - 512)];
}

// ---------------- elementwise ----------------
__global__ void add_skip_kernel(const float* __restrict__ y,
                                float* __restrict__ skip, float* __restrict__ h, int first) {
    int idx = blockIdx.x * 256 + threadIdx.x;
    float v = y[idx];
    skip[idx] = (first ? 0.f : skip[idx]) + v;
    h[idx] += v;
}

// ---------------- fused GAT (xlr packed: xl@0, xr@512, stride 1024) ----------
__global__ void __launch_bounds__(256) gat_fused_kernel(
    const int* __restrict__ edge, const float* __restrict__ xlr,
    const float* __restrict__ att,
    const float* __restrict__ gatb, const float* __restrict__ gamma,
    const float* __restrict__ beta, float* __restrict__ h)
{
    int i = blockIdx.x;
    int tid = threadIdx.x, lane = tid & 31, w = tid >> 5;
    int g = i >> 7, n = i & 127;
    int p0 = d_csr_ptr[n], p1 = d_csr_ptr[n+1];
    int nE = p1 - p0 + 1;     // + self loop (j=0)

    __shared__ float xr_sh[512], att_sh[512];
    __shared__ float2 logit_sh[EE + 1];
    __shared__ float sh_m[2], sh_d[2];
    __shared__ float s_w0[64], s_w1[64];
    __shared__ int   s_si[64];

    xr_sh[tid]       = xlr[(size_t)i*1024 + 512 + tid];
    xr_sh[256 + tid] = xlr[(size_t)i*1024 + 768 + tid];
    att_sh[tid]       = att[tid];
    att_sh[256 + tid] = att[256 + tid];
    __syncthreads();

    // phase A: per-edge logits (warp per edge)
    for (int j = w; j < nE; j += 8) {
        int src = (j == 0) ? i : ((g << 7) + edge[d_csr_eid[p0 + j - 1]]);
        const float* px = xlr + (size_t)src * 1024;
        float s0 = 0.f, s1 = 0.f;
        for (int c = lane; c < 256; c += 32) {
            float v0 = px[c] + xr_sh[c];
            v0 = v0 > 0.f ? v0 : 0.2f * v0;
            s0 = fmaf(att_sh[c], v0, s0);
            float v1 = px[256 + c] + xr_sh[256 + c];
            v1 = v1 > 0.f ? v1 : 0.2f * v1;
            s1 = fmaf(att_sh[256 + c], v1, s1);
        }
#pragma unroll
        for (int o = 16; o; o >>= 1) {
            s0 += __shfl_xor_sync(0xffffffffu, s0, o);
            s1 += __shfl_xor_sync(0xffffffffu, s1, o);
        }
        if (lane == 0) logit_sh[j] = make_float2(s0, s1);
    }
    __syncthreads();

    // phase B: per-head max + denominator
    if (w < 2) {
        float m = -1e30f;
        for (int j = lane; j < nE; j += 32) {
            float lv = (w == 0) ? logit_sh[j].x : logit_sh[j].y;
            m = fmaxf(m, lv);
        }
#pragma unroll
        for (int o = 16; o; o >>= 1) m = fmaxf(m, __shfl_xor_sync(0xffffffffu, m, o));
        float den = 0.f;
        for (int j = lane; j < nE; j += 32) {
            float lv = (w == 0) ? logit_sh[j].x : logit_sh[j].y;
            den += expf(lv - m);
        }
#pragma unroll
        for (int o = 16; o; o >>= 1) den += __shfl_xor_sync(0xffffffffu, den, o);
        if (lane == 0) { sh_m[w] = m; sh_d[w] = den; }
    }
    __syncthreads();

    // phase C: weighted aggregation
    float m0 = sh_m[0], m1 = sh_m[1];
    int c = tid;
    float acc0 = 0.f, acc1 = 0.f;
    for (int ch = 0; ch < nE; ch += 64) {
        int cn = min(64, nE - ch);
        if (tid < cn) {
            int j = ch + tid;
            s_si[tid] = (j == 0) ? i : ((g << 7) + edge[d_csr_eid[p0 + j - 1]]);
            s_w0[tid] = expf(logit_sh[j].x - m0);
            s_w1[tid] = expf(logit_sh[j].y - m1);
        }
        __syncthreads();
        for (int p = 0; p < cn; p++) {
            size_t sb = (size_t)s_si[p] * 1024;
            acc0 = fmaf(s_w0[p], xlr[sb + c], acc0);
            acc1 = fmaf(s_w1[p], xlr[sb + 256 + c], acc1);
        }
        __syncthreads();
    }
    float hg = 0.5f * (acc0 / (sh_d[0] + 1e-16f) + acc1 / (sh_d[1] + 1e-16f)) + gatb[c];
    float v = h[(size_t)i*CC + c] + hg;

    float* sred = att_sh;
    sred[c] = v; __syncthreads();
#pragma unroll
    for (int s = 128; s; s >>= 1) { if (c < s) sred[c] += sred[c + s]; __syncthreads(); }
    float mean = sred[0] * (1.f/256.f); __syncthreads();
    float d = v - mean;
    sred[c] = d * d; __syncthreads();
#pragma unroll
    for (int s = 128; s; s >>= 1) { if (c < s) sred[c] += sred[c + s]; __syncthreads(); }
    float var = sred[0] * (1.f/256.f);
    h[(size_t)i*CC + c] = d * rsqrtf(var + 1e-5f) * gamma[c] + beta[c];
}

// ---------------- MHA: block per (head, bt), smem-staged K^T and V ----------
#define MHA_SMEM ((64*132 + 128*68 + 8*64 + 8*128) * 4)
__global__ void __launch_bounds__(256) mha_kernel(const float* __restrict__ qkv,
                                                  float* __restrict__ aoh) {
    extern __shared__ float sm[];
    float* sKT = sm;                  // [64][132]  (d-major, j contiguous)
    float* sV  = sm + 64*132;         // [128][68]
    float* sQ  = sV + 128*68;         // [8][64]
    float* sP  = sQ + 8*64;           // [8][128]

    int head = blockIdx.x, bt = blockIdx.y;
    int base = bt << 7;
    int off = head << 6;
    int tid = threadIdx.x, lane = tid & 31, w = tid >> 5;

    // stage K transposed
    for (int idx = tid; idx < 128*64; idx += 256) {
        int j = idx >> 6, d = idx & 63;
        sKT[d*132 + j] = qkv[(size_t)(base + j)*768 + 256 + off + d];
    }
    // stage V row-major (float4)
    for (int idx = tid; idx < 128*16; idx += 256) {
        int j = idx >> 4, d4 = (idx & 15) << 2;
        float4 v = *(const float4*)(qkv + (size_t)(base + j)*768 + 512 + off + d4);
        *(float4*)(sV + j*68 + d4) = v;
    }
    __syncthreads();

    for (int it = 0; it < 16; it++) {
        int q = (it << 3) + w;
        sQ[w*64 + lane]      = qkv[(size_t)(base + q)*768 + off + lane];
        sQ[w*64 + 32 + lane] = qkv[(size_t)(base + q)*768 + off + 32 + lane];
        __syncwarp();
        float s0 = 0.f, s1 = 0.f, s2 = 0.f, s3 = 0.f;
#pragma unroll 8
        for (int d = 0; d < 64; d++) {
            float qd = sQ[w*64 + d];
            const float* kr = sKT + d*132;
            s0 = fmaf(qd, kr[lane], s0);
            s1 = fmaf(qd, kr[32 + lane], s1);
            s2 = fmaf(qd, kr[64 + lane], s2);
            s3 = fmaf(qd, kr[96 + lane], s3);
        }
        s0 *= 0.125f; s1 *= 0.125f; s2 *= 0.125f; s3 *= 0.125f;
        float m = fmaxf(fmaxf(s0, s1), fmaxf(s2, s3));
#pragma unroll
        for (int o = 16; o; o >>= 1) m = fmaxf(m, __shfl_xor_sync(0xffffffffu, m, o));
        float e0 = expf(s0 - m), e1 = expf(s1 - m), e2 = expf(s2 - m), e3 = expf(s3 - m);
        float den = e0 + e1 + e2 + e3;
#pragma unroll
        for (int o = 16; o; o >>= 1) den += __shfl_xor_sync(0xffffffffu, den, o);
        float inv = 1.f / den;
        sP[w*128 + lane]      = e0 * inv;
        sP[w*128 + 32 + lane] = e1 * inv;
        sP[w*128 + 64 + lane] = e2 * inv;
        sP[w*128 + 96 + lane] = e3 * inv;
        __syncwarp();
        float o0 = 0.f, o1 = 0.f;
#pragma unroll 4
        for (int j = 0; j < 128; j++) {
            float pw = sP[w*128 + j];
            o0 = fmaf(pw, sV[j*68 + lane], o0);
            o1 = fmaf(pw, sV[j*68 + 32 + lane], o1);
        }
        aoh[(size_t)(base + q)*CC + off + lane]      = o0;
        aoh[(size_t)(base + q)*CC + off + 32 + lane] = o1;
        __syncwarp();
    }
}

// ---------------- residual(skip+h+ao) + LayerNorm ----------------
__global__ void __launch_bounds__(256) resid_ln_kernel(const float* __restrict__ skip,
                                                       const float* __restrict__ h,
                                                       const float* __restrict__ ao,
                                                       const float* __restrict__ gamma,
                                                       const float* __restrict__ beta,
                                                       float* __restrict__ out) {
    int i = blockIdx.x;
    int c = threadIdx.x;
    size_t o = (size_t)i*CC + c;
    float v = skip[o] + h[o] + ao[o];
    __shared__ float sred[256];
    sred[c] = v; __syncthreads();
#pragma unroll
    for (int s = 128; s; s >>= 1) { if (c < s) sred[c] += sred[c + s]; __syncthreads(); }
    float mean = sred[0] * (1.f/256.f); __syncthreads();
    float d = v - mean;
    sred[c] = d * d; __syncthreads();
#pragma unroll
    for (int s = 128; s; s >>= 1) { if (c < s) sred[c] += sred[c + s]; __syncthreads(); }
    float var = sred[0] * (1.f/256.f);
    out[o] = d * rsqrtf(var + 1e-5f) * gamma[c] + beta[c];
}

// ---------------- gate + skip + output head + softplus ----------------
__global__ void __launch_bounds__(256) final_kernel(const float* __restrict__ gpre,
                                                    const float* __restrict__ href,
                                                    const float* __restrict__ skip2,
                                                    const float* __restrict__ W_out,
                                                    const float* __restrict__ b_out,
                                                    float* __restrict__ out) {
    int i = blockIdx.x;
    int c = threadIdx.x;
    float g = 1.f / (1.f + expf(-gpre[(size_t)i*CC + c]));
    float hf = g * href[(size_t)i*CC + c] + (1.f - g) * skip2[(size_t)i*CC + c];
    __shared__ float r0[256], r1[256];
    r0[c] = hf * W_out[c*2 + 0];
    r1[c] = hf * W_out[c*2 + 1];
    __syncthreads();
#pragma unroll
    for (int s = 128; s; s >>= 1) {
        if (c < s) { r0[c] += r0[c + s]; r1[c] += r1[c + s]; }
        __syncthreads();
    }
    if (c == 0) {
        float o0 = r0[0] + b_out[0];
        float o1 = r1[0] + b_out[1];
        out[(size_t)i*2 + 0] = o0;
        out[(size_t)i*2 + 1] = fmaxf(o1, 0.f) + log1pf(expf(-fabsf(o1)));
    }
}

// ---------------- host orchestration ----------------
extern "C" void kernel_launch(void* const* d_in, const int* in_sizes, int n_in,
                              void* d_out, int out_size) {
    const float* x        = (const float*)d_in[0];
    const int*   edge     = (const int*)  d_in[1];
    const float* W_enc    = (const float*)d_in[2];
    const float* b_enc    = (const float*)d_in[3];
    const float* station  = (const float*)d_in[4];
    const float* horizon  = (const float*)d_in[5];
    const float* conv_w   = (const float*)d_in[6];
    const float* conv_b   = (const float*)d_in[7];
    const float* gat_wl   = (const float*)d_in[8];
    const float* gat_wr   = (const float*)d_in[9];
    const float* gat_att  = (const float*)d_in[10];
    const float* gat_b    = (const float*)d_in[11];
    const float* norm_g   = (const float*)d_in[12];
    const float* norm_b   = (const float*)d_in[13];
    const float* Wq       = (const float*)d_in[14];
    const float* Wk       = (const float*)d_in[15];
    const float* Wv       = (const float*)d_in[16];
    const float* Wo       = (const float*)d_in[17];
    const float* bq       = (const float*)d_in[18];
    const float* bk       = (const float*)d_in[19];
    const float* bv       = (const float*)d_in[20];
    const float* bo       = (const float*)d_in[21];
    const float* an_g     = (const float*)d_in[22];
    const float* an_b     = (const float*)d_in[23];
    const float* W_skip   = (const float*)d_in[24];
    const float* b_skip   = (const float*)d_in[25];
    const float* W_gate   = (const float*)d_in[26];
    const float* b_gate   = (const float*)d_in[27];
    const float* W_out    = (const float*)d_in[28];
    const float* b_out    = (const float*)d_in[29];
    float* out = (float*)d_out;

    float* buf = nullptr;
    cudaGetSymbolAddress((void**)&buf, d_buf);
    float* g_h    = buf + OFF_H;
    float* g_skip = buf + OFF_SKIP;
    float* g_y    = buf + OFF_Y;
    float* g_xlr  = buf + OFF_XLR;
    float* g_qkv  = buf + OFF_QKV;
    float* g_ao   = buf + OFF_AO;
    float* g_href = buf + OFF_HREF;
    float* g_wt   = buf + OFF_WT;
    float* g_wqkv = buf + OFF_WQKV;
    float* g_bqkv = buf + OFF_BQKV;
    float* g_wlr  = buf + OFF_WLR;

    const dim3 thr(256);
    const dim3 gN256(CC/64, NNODE/128);           // (4, 96)
    const dim3 gN768(768/64, NNODE/128);          // (12, 96)
    const dim3 gN1024(1024/64, NNODE/128);        // (16, 96)
    const int EW = NNODE;

    cudaFuncSetAttribute(mha_kernel, cudaFuncAttributeMaxDynamicSharedMemorySize, MHA_SMEM);

    build_csr_kernel<<<1, NST>>>(edge);
    transpose_w_all<<<(LL*KK*CC*CC)/256, thr>>>(conv_w, g_wt);
    pack_qkv_kernel<<<(CC*768)/256, thr>>>(Wq, Wk, Wv, bq, bk, bv, g_wqkv, g_bqkv);
    pack_wlr_kernel<<<(LL*CC*1024)/256, thr>>>(gat_wl, gat_wr, g_wlr);

    // encoder: h = x @ W_enc + b_enc + station + horizon
    gemm_tc<1,0><<<gN256, thr>>>(x, nullptr, W_enc, b_enc, g_h, CC, FINF, 0,
                                 station, horizon);

    for (int l = 0; l < LL; l++) {
        int dil = 1 << l;
        gemm_tc<2,1><<<gN256, thr>>>(g_h, nullptr, g_wt + (size_t)l*KK*CC*CC,
                                     conv_b + l*CC, g_y, CC, KK*CC, dil, nullptr, nullptr);
        add_skip_kernel<<<EW, thr>>>(g_y, g_skip, g_h, l == 0 ? 1 : 0);
        gemm_tc<0,0><<<gN1024, thr>>>(g_h, nullptr, g_wlr + (size_t)l*CC*1024, nullptr,
                                      g_xlr, 1024, CC, 0, nullptr, nullptr);
        gat_fused_kernel<<<NNODE, thr>>>(edge, g_xlr, gat_att + l*GHH*CC,
                                         gat_b + l*CC, norm_g + l*CC, norm_b + l*CC, g_h);
    }

    // QKV in one GEMM, A = skip + h (fused)
    gemm_tc<0,2><<<gN768, thr>>>(g_skip, g_h, g_wqkv, g_bqkv, g_qkv, 768, CC, 0,
                                 nullptr, nullptr);
    mha_kernel<<<dim3(NHH, NG), thr, MHA_SMEM>>>(g_qkv, g_xlr);   // ao-heads -> g_xlr
    gemm_tc<0,0><<<gN256, thr>>>(g_xlr, nullptr, Wo, bo, g_ao, CC, CC, 0, nullptr, nullptr);
    resid_ln_kernel<<<NNODE, thr>>>(g_skip, g_h, g_ao, an_g, an_b, g_href);

    // gate + skip branch + output head
    gemm_tc<0,0><<<gN256, thr>>>(x, nullptr, W_skip, b_skip, g_y, CC, FINF, 0,
                                 nullptr, nullptr);
    gemm_tc<0,0><<<gN256, thr>>>(g_href, nullptr, W_gate, b_gate, g_qkv, CC, CC, 0,
                                 nullptr, nullptr);
    final_kernel<<<NNODE, thr>>>(g_qkv, g_href, g_y, W_out, b_out, out);

    (void)in_sizes; (void)n_in; (void)out_size;
}

// round 4
// speedup vs baseline: 2.8918x; 1.0808x over previous
#include <cuda_runtime.h>
#include <math.h>
#include <stdint.h>

// ---------------- problem constants ----------------
#define BBATCH 4
#define TT     24
#define NST    128
#define FINF   64
#define CC     256
#define LL     3
#define KK     3
#define GHH    2
#define NHH    4
#define EE     1024
#define NG     (BBATCH*TT)        // 96
#define NNODE  (NG*NST)           // 12288

// ---------------- static scratch ----------------
__device__ int d_csr_ptr[NST+1];
__device__ int d_csr_eid[EE];

#define OFF_H    ((size_t)0)
#define OFF_H2   (OFF_H    + (size_t)NNODE*CC)
#define OFF_SKIP (OFF_H2   + (size_t)NNODE*CC)
#define OFF_Y    (OFF_SKIP + (size_t)NNODE*CC)
#define OFF_XLR  (OFF_Y    + (size_t)NNODE*CC)
#define OFF_QKV  (OFF_XLR  + (size_t)NNODE*1024)
#define OFF_AO   (OFF_QKV  + (size_t)NNODE*768)
#define OFF_HREF (OFF_AO   + (size_t)NNODE*CC)
#define OFF_BQKV (OFF_HREF + (size_t)NNODE*CC)
#define TOTF     (OFF_BQKV + (size_t)768)
__device__ float d_buf[TOTF];

// pre-split (hi,lo) tf32 weights
#define W2_WT    ((size_t)0)                               // 3 * 768 * 256
#define W2_WLR   (W2_WT   + (size_t)LL*KK*CC*CC)           // 3 * 256 * 1024
#define W2_QKV   (W2_WLR  + (size_t)LL*CC*1024)            // 256 * 768
#define W2_ENC   (W2_QKV  + (size_t)CC*768)                // 64 * 256
#define W2_SKIP  (W2_ENC  + (size_t)FINF*CC)
#define W2_WO    (W2_SKIP + (size_t)FINF*CC)               // 256 * 256
#define W2_GATE  (W2_WO   + (size_t)CC*CC)
#define TOTW2    (W2_GATE + (size_t)CC*CC)
__device__ float2 d_wbuf[TOTW2];

// ---------------- helpers ----------------
__device__ __forceinline__ float tf32r(float x) {
    uint32_t u;
    asm("cvt.rna.tf32.f32 %0, %1;" : "=r"(u) : "f"(x));
    return __uint_as_float(u);
}
__device__ __forceinline__ float2 split2(float v) {
    float h = tf32r(v);
    return make_float2(h, tf32r(v - h));
}
#define U32F(f) __float_as_uint(f)

__device__ __forceinline__ void mma8(float4& d, const uint32_t a[4],
                                     uint32_t b0, uint32_t b1) {
    asm volatile(
        "mma.sync.aligned.m16n8k8.row.col.f32.tf32.tf32.f32 "
        "{%0,%1,%2,%3},{%4,%5,%6,%7},{%8,%9},{%0,%1,%2,%3};"
        : "+f"(d.x), "+f"(d.y), "+f"(d.z), "+f"(d.w)
        : "r"(a[0]), "r"(a[1]), "r"(a[2]), "r"(a[3]), "r"(b0), "r"(b1));
}

__device__ __forceinline__ void cpa16(uint32_t dst, const void* src) {
    asm volatile("cp.async.ca.shared.global [%0], [%1], 16;" :: "r"(dst), "l"(src));
}
__device__ __forceinline__ void cpa16z(uint32_t dst, const void* src, int sz) {
    asm volatile("cp.async.ca.shared.global [%0], [%1], 16, %2;"
                 :: "r"(dst), "l"(src), "r"(sz));
}
#define CPA_COMMIT() asm volatile("cp.async.commit_group;" ::: "memory")
#define CPA_WAIT(n)  asm volatile("cp.async.wait_group %0;" :: "n"(n) : "memory")

// ---------------- deterministic CSR of base graph ----------------
__global__ void build_csr_kernel(const int* __restrict__ edge) {
    const int* dst = edge + EE;
    int n = threadIdx.x;             // 0..127
    __shared__ int counts[NST];
    int cnt = 0;
    for (int e = 0; e < EE; e++) if (dst[e] == n) cnt++;
    counts[n] = cnt;
    __syncthreads();
    if (n == 0) {
        int s = 0;
        for (int i = 0; i < NST; i++) { d_csr_ptr[i] = s; s += counts[i]; }
        d_csr_ptr[NST] = s;
    }
    __syncthreads();
    int p = d_csr_ptr[n];
    for (int e = 0; e < EE; e++) if (dst[e] == n) d_csr_eid[p++] = e;  // stable
}

// ---------------- tf32 GEMM, double-buffered cp.async, pre-split B -----------
// BM=128 BN=64 BK=16, 256 thr, warps 4x2, warp tile 32x32. 2-term split on B.
// EPI: 0 = +bias, 1 = +bias+station+horizon, 3 = conv fused (relu, h+=, skip+=)
// AMODE: 0 = plain A, 1 = conv gather (dil), 2 = A + A2
template<int EPI, int AMODE>
__global__ void __launch_bounds__(256, 3) gemm_tc(
    const float* __restrict__ A, const float* __restrict__ A2,
    const float2* __restrict__ B, const float* __restrict__ bias,
    float* __restrict__ C, int N, int Kd, int dil, int first,
    float* __restrict__ skipb,
    const float* __restrict__ aux1, const float* __restrict__ aux2)
{
    __shared__ float  As[2][128][20];
    __shared__ float2 Bs[2][16][68];

    int tid = threadIdx.x, lane = tid & 31, w = tid >> 5;
    int bm = blockIdx.y << 7, bn = blockIdx.x << 6;
    int wm = w >> 1, wn = w & 1;
    int r = lane >> 2, cg = lane & 3;

    float4 acc[2][4];
#pragma unroll
    for (int mt = 0; mt < 2; mt++)
#pragma unroll
        for (int nt = 0; nt < 4; nt++) acc[mt][nt] = make_float4(0.f, 0.f, 0.f, 0.f);

    int arow = tid >> 2, akq = (tid & 3) << 2;
    int KT = Kd >> 4;

    auto loadA = [&](int kt, int st) {
        int k0 = kt << 4;
#pragma unroll
        for (int i = 0; i < 2; i++) {
            int m = arow + (i << 6);
            uint32_t dst = (uint32_t)__cvta_generic_to_shared(&As[st][m][akq]);
            if (AMODE == 1) {
                int kg = k0 + akq;
                int tap = kg >> 8;
                int shift = (2 - tap) * dil;
                int node = bm + m;
                int t = (node >> 7) % TT;
                bool ok = (t >= shift);
                const float* src = ok ? (A + (size_t)(node - (shift << 7)) * CC + (kg & 255)) : A;
                cpa16z(dst, src, ok ? 16 : 0);
            } else if (AMODE == 2) {
                size_t off = (size_t)(bm + m) * Kd + k0 + akq;
                float4 a = *(const float4*)(A + off);
                float4 b = *(const float4*)(A2 + off);
                *(float4*)&As[st][m][akq] =
                    make_float4(a.x + b.x, a.y + b.y, a.z + b.z, a.w + b.w);
            } else {
                cpa16(dst, A + (size_t)(bm + m) * Kd + k0 + akq);
            }
        }
    };
    auto loadB = [&](int kt, int st) {
        int k0 = kt << 4;
#pragma unroll
        for (int i = 0; i < 2; i++) {
            int idx = tid + (i << 8);
            int kr = idx >> 5, c2 = (idx & 31) << 1;
            uint32_t dst = (uint32_t)__cvta_generic_to_shared(&Bs[st][kr][c2]);
            cpa16(dst, B + (size_t)(k0 + kr) * N + bn + c2);
        }
    };

    loadA(0, 0); loadB(0, 0);
    CPA_COMMIT();

    for (int kt = 0; kt < KT; kt++) {
        int st = kt & 1;
        if (kt + 1 < KT) {
            loadA(kt + 1, st ^ 1); loadB(kt + 1, st ^ 1);
            CPA_COMMIT();
            CPA_WAIT(1);
        } else {
            CPA_WAIT(0);
        }
        __syncthreads();
#pragma unroll
        for (int kk = 0; kk < 16; kk += 8) {
            uint32_t ah[2][4];
#pragma unroll
            for (int mt = 0; mt < 2; mt++) {
                int m = (wm << 5) + (mt << 4) + r;
                ah[mt][0] = U32F(tf32r(As[st][m][kk+cg]));
                ah[mt][1] = U32F(tf32r(As[st][m+8][kk+cg]));
                ah[mt][2] = U32F(tf32r(As[st][m][kk+cg+4]));
                ah[mt][3] = U32F(tf32r(As[st][m+8][kk+cg+4]));
            }
#pragma unroll
            for (int nt = 0; nt < 4; nt++) {
                int n = (wn << 5) + (nt << 3) + r;
                float2 b0 = Bs[st][kk+cg  ][n];
                float2 b1 = Bs[st][kk+cg+4][n];
#pragma unroll
                for (int mt = 0; mt < 2; mt++) {
                    mma8(acc[mt][nt], ah[mt], U32F(b0.x), U32F(b1.x));
                    mma8(acc[mt][nt], ah[mt], U32F(b0.y), U32F(b1.y));
                }
            }
        }
        __syncthreads();
    }

    // ---- epilogue ----
#pragma unroll
    for (int mt = 0; mt < 2; mt++) {
        int m0 = bm + (wm << 5) + (mt << 4) + r;
        int m1 = m0 + 8;
#pragma unroll
        for (int nt = 0; nt < 4; nt++) {
            int col = bn + (wn << 5) + (nt << 3) + (cg << 1);
            float b0 = bias ? bias[col] : 0.f;
            float b1 = bias ? bias[col+1] : 0.f;
            float2 v0 = make_float2(acc[mt][nt].x + b0, acc[mt][nt].y + b1);
            float2 v1 = make_float2(acc[mt][nt].z + b0, acc[mt][nt].w + b1);
            if (EPI == 1) {
                int s0 = (m0 & 127) * CC + col, t0 = ((m0 >> 7) % TT) * CC + col;
                int s1 = (m1 & 127) * CC + col, t1 = ((m1 >> 7) % TT) * CC + col;
                v0.x += aux1[s0] + aux2[t0];     v0.y += aux1[s0+1] + aux2[t0+1];
                v1.x += aux1[s1] + aux2[t1];     v1.y += aux1[s1+1] + aux2[t1+1];
            }
            if (EPI == 3) {
                v0.x = fmaxf(v0.x, 0.f); v0.y = fmaxf(v0.y, 0.f);
                v1.x = fmaxf(v1.x, 0.f); v1.y = fmaxf(v1.y, 0.f);
                size_t o0 = (size_t)m0 * CC + col, o1 = (size_t)m1 * CC + col;
                float2 h0 = *(const float2*)(A + o0);
                float2 h1 = *(const float2*)(A + o1);
                *(float2*)(C + o0) = make_float2(h0.x + v0.x, h0.y + v0.y);
                *(float2*)(C + o1) = make_float2(h1.x + v1.x, h1.y + v1.y);
                float2 s0, s1;
                if (first) { s0 = v0; s1 = v1; }
                else {
                    float2 p0 = *(const float2*)(skipb + o0);
                    float2 p1 = *(const float2*)(skipb + o1);
                    s0 = make_float2(p0.x + v0.x, p0.y + v0.y);
                    s1 = make_float2(p1.x + v1.x, p1.y + v1.y);
                }
                *(float2*)(skipb + o0) = s0;
                *(float2*)(skipb + o1) = s1;
            } else {
                *(float2*)(C + (size_t)m0 * N + col) = v0;
                *(float2*)(C + (size_t)m1 * N + col) = v1;
            }
        }
    }
}

// ---------------- weight prep (write pre-split float2) ----------------
__global__ void transpose_w_all(const float* __restrict__ w, float2* __restrict__ wt) {
    int idx = blockIdx.x * 256 + threadIdx.x;        // < 3*3*256*256
    int l = idx / (KK*CC*CC);
    int rem = idx - l * (KK*CC*CC);
    int tap = rem >> 16;
    int cin = (rem >> 8) & 255;
    int cout = rem & 255;
    wt[idx] = split2(w[(((size_t)l*CC + cout)*CC + cin)*KK + tap]);
}

__global__ void pack_qkv_kernel(const float* __restrict__ Wq, const float* __restrict__ Wk,
                                const float* __restrict__ Wv, const float* __restrict__ bq,
                                const float* __restrict__ bk, const float* __restrict__ bv,
                                float2* __restrict__ W, float* __restrict__ b) {
    int idx = blockIdx.x * 256 + threadIdx.x;        // < 256*768
    int k = idx / 768, n = idx - k * 768;
    int sel = n >> 8, nn = n & 255;
    const float* src = sel == 0 ? Wq : (sel == 1 ? Wk : Wv);
    W[idx] = split2(src[k * CC + nn]);
    if (idx < 768) {
        const float* bs = sel == 0 ? bq : (sel == 1 ? bk : bv);
        b[idx] = bs[nn];
    }
}

__global__ void pack_wlr_kernel(const float* __restrict__ wl, const float* __restrict__ wr,
                                float2* __restrict__ W) {
    int idx = blockIdx.x * 256 + threadIdx.x;        // < 3*256*1024
    int l = idx >> 18;
    int rem = idx & 262143;
    int k = rem >> 10, n = rem & 1023;
    float v = (n < 512) ? wl[(size_t)l*CC*512 + k*512 + n]
                        : wr[(size_t)l*CC*512 + k*512 + (n - 512)];
    W[idx] = split2(v);
}

__global__ void split_plain(const float* __restrict__ in, float2* __restrict__ out, int n) {
    int i = blockIdx.x * 256 + threadIdx.x;
    if (i < n) out[i] = split2(in[i]);
}

// ---------------- fused GAT (xlr packed: xl@0, xr@512, stride 1024) ----------
__global__ void __launch_bounds__(256) gat_fused_kernel(
    const int* __restrict__ edge, const float* __restrict__ xlr,
    const float* __restrict__ att,
    const float* __restrict__ gatb, const float* __restrict__ gamma,
    const float* __restrict__ beta, float* __restrict__ h)
{
    int i = blockIdx.x;
    int tid = threadIdx.x, lane = tid & 31, w = tid >> 5;
    int g = i >> 7, n = i & 127;
    int p0 = d_csr_ptr[n], p1 = d_csr_ptr[n+1];
    int nE = p1 - p0 + 1;     // + self loop (j=0)

    __shared__ float xr_sh[512], att_sh[512];
    __shared__ float2 logit_sh[EE + 1];
    __shared__ float sh_m[2], sh_d[2];
    __shared__ float s_w0[64], s_w1[64];
    __shared__ int   s_si[64];

    xr_sh[tid]       = xlr[(size_t)i*1024 + 512 + tid];
    xr_sh[256 + tid] = xlr[(size_t)i*1024 + 768 + tid];
    att_sh[tid]       = att[tid];
    att_sh[256 + tid] = att[256 + tid];
    __syncthreads();

    for (int j = w; j < nE; j += 8) {
        int src = (j == 0) ? i : ((g << 7) + edge[d_csr_eid[p0 + j - 1]]);
        const float* px = xlr + (size_t)src * 1024;
        float s0 = 0.f, s1 = 0.f;
        for (int c = lane; c < 256; c += 32) {
            float v0 = px[c] + xr_sh[c];
            v0 = v0 > 0.f ? v0 : 0.2f * v0;
            s0 = fmaf(att_sh[c], v0, s0);
            float v1 = px[256 + c] + xr_sh[256 + c];
            v1 = v1 > 0.f ? v1 : 0.2f * v1;
            s1 = fmaf(att_sh[256 + c], v1, s1);
        }
#pragma unroll
        for (int o = 16; o; o >>= 1) {
            s0 += __shfl_xor_sync(0xffffffffu, s0, o);
            s1 += __shfl_xor_sync(0xffffffffu, s1, o);
        }
        if (lane == 0) logit_sh[j] = make_float2(s0, s1);
    }
    __syncthreads();

    if (w < 2) {
        float m = -1e30f;
        for (int j = lane; j < nE; j += 32) {
            float lv = (w == 0) ? logit_sh[j].x : logit_sh[j].y;
            m = fmaxf(m, lv);
        }
#pragma unroll
        for (int o = 16; o; o >>= 1) m = fmaxf(m, __shfl_xor_sync(0xffffffffu, m, o));
        float den = 0.f;
        for (int j = lane; j < nE; j += 32) {
            float lv = (w == 0) ? logit_sh[j].x : logit_sh[j].y;
            den += expf(lv - m);
        }
#pragma unroll
        for (int o = 16; o; o >>= 1) den += __shfl_xor_sync(0xffffffffu, den, o);
        if (lane == 0) { sh_m[w] = m; sh_d[w] = den; }
    }
    __syncthreads();

    float m0 = sh_m[0], m1 = sh_m[1];
    int c = tid;
    float acc0 = 0.f, acc1 = 0.f;
    for (int ch = 0; ch < nE; ch += 64) {
        int cn = min(64, nE - ch);
        if (tid < cn) {
            int j = ch + tid;
            s_si[tid] = (j == 0) ? i : ((g << 7) + edge[d_csr_eid[p0 + j - 1]]);
            s_w0[tid] = expf(logit_sh[j].x - m0);
            s_w1[tid] = expf(logit_sh[j].y - m1);
        }
        __syncthreads();
        for (int p = 0; p < cn; p++) {
            size_t sb = (size_t)s_si[p] * 1024;
            acc0 = fmaf(s_w0[p], xlr[sb + c], acc0);
            acc1 = fmaf(s_w1[p], xlr[sb + 256 + c], acc1);
        }
        __syncthreads();
    }
    float hg = 0.5f * (acc0 / (sh_d[0] + 1e-16f) + acc1 / (sh_d[1] + 1e-16f)) + gatb[c];
    float v = h[(size_t)i*CC + c] + hg;

    float* sred = att_sh;
    sred[c] = v; __syncthreads();
#pragma unroll
    for (int s = 128; s; s >>= 1) { if (c < s) sred[c] += sred[c + s]; __syncthreads(); }
    float mean = sred[0] * (1.f/256.f); __syncthreads();
    float d = v - mean;
    sred[c] = d * d; __syncthreads();
#pragma unroll
    for (int s = 128; s; s >>= 1) { if (c < s) sred[c] += sred[c + s]; __syncthreads(); }
    float var = sred[0] * (1.f/256.f);
    h[(size_t)i*CC + c] = d * rsqrtf(var + 1e-5f) * gamma[c] + beta[c];
}

// ---------------- MHA: block per (head, bt), smem-staged K^T and V ----------
#define MHA_SMEM ((64*132 + 128*68 + 8*64 + 8*128) * 4)
__global__ void __launch_bounds__(256) mha_kernel(const float* __restrict__ qkv,
                                                  float* __restrict__ aoh) {
    extern __shared__ float sm[];
    float* sKT = sm;                  // [64][132]
    float* sV  = sm + 64*132;         // [128][68]
    float* sQ  = sV + 128*68;         // [8][64]
    float* sP  = sQ + 8*64;           // [8][128]

    int head = blockIdx.x, bt = blockIdx.y;
    int base = bt << 7;
    int off = head << 6;
    int tid = threadIdx.x, lane = tid & 31, w = tid >> 5;

    for (int idx = tid; idx < 128*64; idx += 256) {
        int j = idx >> 6, d = idx & 63;
        sKT[d*132 + j] = qkv[(size_t)(base + j)*768 + 256 + off + d];
    }
    for (int idx = tid; idx < 128*16; idx += 256) {
        int j = idx >> 4, d4 = (idx & 15) << 2;
        float4 v = *(const float4*)(qkv + (size_t)(base + j)*768 + 512 + off + d4);
        *(float4*)(sV + j*68 + d4) = v;
    }
    __syncthreads();

    for (int it = 0; it < 16; it++) {
        int q = (it << 3) + w;
        sQ[w*64 + lane]      = qkv[(size_t)(base + q)*768 + off + lane];
        sQ[w*64 + 32 + lane] = qkv[(size_t)(base + q)*768 + off + 32 + lane];
        __syncwarp();
        float s0 = 0.f, s1 = 0.f, s2 = 0.f, s3 = 0.f;
#pragma unroll 8
        for (int d = 0; d < 64; d++) {
            float qd = sQ[w*64 + d];
            const float* kr = sKT + d*132;
            s0 = fmaf(qd, kr[lane], s0);
            s1 = fmaf(qd, kr[32 + lane], s1);
            s2 = fmaf(qd, kr[64 + lane], s2);
            s3 = fmaf(qd, kr[96 + lane], s3);
        }
        s0 *= 0.125f; s1 *= 0.125f; s2 *= 0.125f; s3 *= 0.125f;
        float m = fmaxf(fmaxf(s0, s1), fmaxf(s2, s3));
#pragma unroll
        for (int o = 16; o; o >>= 1) m = fmaxf(m, __shfl_xor_sync(0xffffffffu, m, o));
        float e0 = expf(s0 - m), e1 = expf(s1 - m), e2 = expf(s2 - m), e3 = expf(s3 - m);
        float den = e0 + e1 + e2 + e3;
#pragma unroll
        for (int o = 16; o; o >>= 1) den += __shfl_xor_sync(0xffffffffu, den, o);
        float inv = 1.f / den;
        sP[w*128 + lane]      = e0 * inv;
        sP[w*128 + 32 + lane] = e1 * inv;
        sP[w*128 + 64 + lane] = e2 * inv;
        sP[w*128 + 96 + lane] = e3 * inv;
        __syncwarp();
        float o0 = 0.f, o1 = 0.f;
#pragma unroll 4
        for (int j = 0; j < 128; j++) {
            float pw = sP[w*128 + j];
            o0 = fmaf(pw, sV[j*68 + lane], o0);
            o1 = fmaf(pw, sV[j*68 + 32 + lane], o1);
        }
        aoh[(size_t)(base + q)*CC + off + lane]      = o0;
        aoh[(size_t)(base + q)*CC + off + 32 + lane] = o1;
        __syncwarp();
    }
}

// ---------------- residual(skip+h+ao) + LayerNorm ----------------
__global__ void __launch_bounds__(256) resid_ln_kernel(const float* __restrict__ skip,
                                                       const float* __restrict__ h,
                                                       const float* __restrict__ ao,
                                                       const float* __restrict__ gamma,
                                                       const float* __restrict__ beta,
                                                       float* __restrict__ out) {
    int i = blockIdx.x;
    int c = threadIdx.x;
    size_t o = (size_t)i*CC + c;
    float v = skip[o] + h[o] + ao[o];
    __shared__ float sred[256];
    sred[c] = v; __syncthreads();
#pragma unroll
    for (int s = 128; s; s >>= 1) { if (c < s) sred[c] += sred[c + s]; __syncthreads(); }
    float mean = sred[0] * (1.f/256.f); __syncthreads();
    float d = v - mean;
    sred[c] = d * d; __syncthreads();
#pragma unroll
    for (int s = 128; s; s >>= 1) { if (c < s) sred[c] += sred[c + s]; __syncthreads(); }
    float var = sred[0] * (1.f/256.f);
    out[o] = d * rsqrtf(var + 1e-5f) * gamma[c] + beta[c];
}

// ---------------- gate + skip + output head + softplus ----------------
__global__ void __launch_bounds__(256) final_kernel(const float* __restrict__ gpre,
                                                    const float* __restrict__ href,
                                                    const float* __restrict__ skip2,
                                                    const float* __restrict__ W_out,
                                                    const float* __restrict__ b_out,
                                                    float* __restrict__ out) {
    int i = blockIdx.x;
    int c = threadIdx.x;
    float g = 1.f / (1.f + expf(-gpre[(size_t)i*CC + c]));
    float hf = g * href[(size_t)i*CC + c] + (1.f - g) * skip2[(size_t)i*CC + c];
    __shared__ float r0[256], r1[256];
    r0[c] = hf * W_out[c*2 + 0];
    r1[c] = hf * W_out[c*2 + 1];
    __syncthreads();
#pragma unroll
    for (int s = 128; s; s >>= 1) {
        if (c < s) { r0[c] += r0[c + s]; r1[c] += r1[c + s]; }
        __syncthreads();
    }
    if (c == 0) {
        float o0 = r0[0] + b_out[0];
        float o1 = r1[0] + b_out[1];
        out[(size_t)i*2 + 0] = o0;
        out[(size_t)i*2 + 1] = fmaxf(o1, 0.f) + log1pf(expf(-fabsf(o1)));
    }
}

// ---------------- host orchestration ----------------
extern "C" void kernel_launch(void* const* d_in, const int* in_sizes, int n_in,
                              void* d_out, int out_size) {
    const float* x        = (const float*)d_in[0];
    const int*   edge     = (const int*)  d_in[1];
    const float* W_enc    = (const float*)d_in[2];
    const float* b_enc    = (const float*)d_in[3];
    const float* station  = (const float*)d_in[4];
    const float* horizon  = (const float*)d_in[5];
    const float* conv_w   = (const float*)d_in[6];
    const float* conv_b   = (const float*)d_in[7];
    const float* gat_wl   = (const float*)d_in[8];
    const float* gat_wr   = (const float*)d_in[9];
    const float* gat_att  = (const float*)d_in[10];
    const float* gat_b    = (const float*)d_in[11];
    const float* norm_g   = (const float*)d_in[12];
    const float* norm_b   = (const float*)d_in[13];
    const float* Wq       = (const float*)d_in[14];
    const float* Wk       = (const float*)d_in[15];
    const float* Wv       = (const float*)d_in[16];
    const float* Wo       = (const float*)d_in[17];
    const float* bq       = (const float*)d_in[18];
    const float* bk       = (const float*)d_in[19];
    const float* bv       = (const float*)d_in[20];
    const float* bo       = (const float*)d_in[21];
    const float* an_g     = (const float*)d_in[22];
    const float* an_b     = (const float*)d_in[23];
    const float* W_skip   = (const float*)d_in[24];
    const float* b_skip   = (const float*)d_in[25];
    const float* W_gate   = (const float*)d_in[26];
    const float* b_gate   = (const float*)d_in[27];
    const float* W_out    = (const float*)d_in[28];
    const float* b_out    = (const float*)d_in[29];
    float* out = (float*)d_out;

    float* buf = nullptr;
    cudaGetSymbolAddress((void**)&buf, d_buf);
    float2* wbuf = nullptr;
    cudaGetSymbolAddress((void**)&wbuf, d_wbuf);

    float* g_h    = buf + OFF_H;
    float* g_h2   = buf + OFF_H2;
    float* g_skip = buf + OFF_SKIP;
    float* g_y    = buf + OFF_Y;
    float* g_xlr  = buf + OFF_XLR;
    float* g_qkv  = buf + OFF_QKV;
    float* g_ao   = buf + OFF_AO;
    float* g_href = buf + OFF_HREF;
    float* g_bqkv = buf + OFF_BQKV;

    float2* w_wt   = wbuf + W2_WT;
    float2* w_wlr  = wbuf + W2_WLR;
    float2* w_qkv  = wbuf + W2_QKV;
    float2* w_enc  = wbuf + W2_ENC;
    float2* w_skip = wbuf + W2_SKIP;
    float2* w_wo   = wbuf + W2_WO;
    float2* w_gate = wbuf + W2_GATE;

    const dim3 thr(256);
    const dim3 gN256(CC/64, NNODE/128);           // (4, 96)
    const dim3 gN768(768/64, NNODE/128);          // (12, 96)
    const dim3 gN1024(1024/64, NNODE/128);        // (16, 96)

    cudaFuncSetAttribute(mha_kernel, cudaFuncAttributeMaxDynamicSharedMemorySize, MHA_SMEM);

    build_csr_kernel<<<1, NST>>>(edge);
    transpose_w_all<<<(LL*KK*CC*CC)/256, thr>>>(conv_w, w_wt);
    pack_qkv_kernel<<<(CC*768)/256, thr>>>(Wq, Wk, Wv, bq, bk, bv, w_qkv, g_bqkv);
    pack_wlr_kernel<<<(LL*CC*1024)/256, thr>>>(gat_wl, gat_wr, w_wlr);
    split_plain<<<(FINF*CC)/256, thr>>>(W_enc, w_enc, FINF*CC);
    split_plain<<<(FINF*CC)/256, thr>>>(W_skip, w_skip, FINF*CC);
    split_plain<<<(CC*CC)/256, thr>>>(Wo, w_wo, CC*CC);
    split_plain<<<(CC*CC)/256, thr>>>(W_gate, w_gate, CC*CC);

    // encoder: h = x @ W_enc + b_enc + station + horizon
    gemm_tc<1,0><<<gN256, thr>>>(x, nullptr, w_enc, b_enc, g_h, CC, FINF, 0, 0,
                                 nullptr, station, horizon);

    float* hcur = g_h;
    float* hnext = g_h2;
    for (int l = 0; l < LL; l++) {
        int dil = 1 << l;
        // conv fused: hnext = hcur + relu(conv(hcur)); skip (+)= relu(conv)
        gemm_tc<3,1><<<gN256, thr>>>(hcur, nullptr, w_wt + (size_t)l*KK*CC*CC,
                                     conv_b + l*CC, hnext, CC, KK*CC, dil, l == 0,
                                     g_skip, nullptr, nullptr);
        gemm_tc<0,0><<<gN1024, thr>>>(hnext, nullptr, w_wlr + (size_t)l*CC*1024, nullptr,
                                      g_xlr, 1024, CC, 0, 0, nullptr, nullptr, nullptr);
        gat_fused_kernel<<<NNODE, thr>>>(edge, g_xlr, gat_att + l*GHH*CC,
                                         gat_b + l*CC, norm_g + l*CC, norm_b + l*CC, hnext);
        float* tmp = hcur; hcur = hnext; hnext = tmp;
    }
    // hcur now holds final h_tcn

    // QKV in one GEMM, A = skip + h (fused)
    gemm_tc<0,2><<<gN768, thr>>>(g_skip, hcur, w_qkv, g_bqkv, g_qkv, 768, CC, 0, 0,
                                 nullptr, nullptr, nullptr);
    mha_kernel<<<dim3(NHH, NG), thr, MHA_SMEM>>>(g_qkv, g_xlr);
    gemm_tc<0,0><<<gN256, thr>>>(g_xlr, nullptr, w_wo, bo, g_ao, CC, CC, 0, 0,
                                 nullptr, nullptr, nullptr);
    resid_ln_kernel<<<NNODE, thr>>>(g_skip, hcur, g_ao, an_g, an_b, g_href);

    // gate + skip branch + output head
    gemm_tc<0,0><<<gN256, thr>>>(x, nullptr, w_skip, b_skip, g_y, CC, FINF, 0, 0,
                                 nullptr, nullptr, nullptr);
    gemm_tc<0,0><<<gN256, thr>>>(g_href, nullptr, w_gate, b_gate, g_qkv, CC, CC, 0, 0,
                                 nullptr, nullptr, nullptr);
    final_kernel<<<NNODE, thr>>>(g_qkv, g_href, g_y, W_out, b_out, out);

    (void)in_sizes; (void)n_in; (void)out_size;
}

// round 5
// speedup vs baseline: 2.9599x; 1.0235x over previous
#include <cuda_runtime.h>
#include <math.h>
#include <stdint.h>

// ---------------- problem constants ----------------
#define BBATCH 4
#define TT     24
#define NST    128
#define FINF   64
#define CC     256
#define LL     3
#define KK     3
#define GHH    2
#define NHH    4
#define EE     1024
#define NG     (BBATCH*TT)        // 96
#define NNODE  (NG*NST)           // 12288
#define MAXE   64                 // max in-degree bound (mean 8)
#define ECAP   24                 // smem-cached edges per node

// ---------------- static scratch ----------------
__device__ int d_csr_ptr[NST+1];
__device__ int d_csr_eid[EE];

#define OFF_H    ((size_t)0)
#define OFF_H2   (OFF_H    + (size_t)NNODE*CC)
#define OFF_SKIP (OFF_H2   + (size_t)NNODE*CC)
#define OFF_Y    (OFF_SKIP + (size_t)NNODE*CC)
#define OFF_XLR  (OFF_Y    + (size_t)NNODE*CC)
#define OFF_QKV  (OFF_XLR  + (size_t)NNODE*1024)
#define OFF_AO   (OFF_QKV  + (size_t)NNODE*768)
#define OFF_HREF (OFF_AO   + (size_t)NNODE*CC)
#define OFF_BQKV (OFF_HREF + (size_t)NNODE*CC)
#define TOTF     (OFF_BQKV + (size_t)768)
__device__ float d_buf[TOTF];

// conv weights: pre-split (hi,lo) float2
__device__ float2 d_wbuf2[(size_t)LL*KK*CC*CC];
// all other weights: tf32-rounded float
#define WF_WLR  ((size_t)0)                        // 3*256*1024
#define WF_QKV  (WF_WLR  + (size_t)LL*CC*1024)     // 256*768
#define WF_ENC  (WF_QKV  + (size_t)CC*768)         // 64*256
#define WF_SKIP (WF_ENC  + (size_t)FINF*CC)
#define WF_WO   (WF_SKIP + (size_t)FINF*CC)        // 256*256
#define WF_GATE (WF_WO   + (size_t)CC*CC)
#define TOTWF   (WF_GATE + (size_t)CC*CC)
__device__ float d_wbuf1[TOTWF];

// ---------------- helpers ----------------
__device__ __forceinline__ float tf32r(float x) {
    uint32_t u;
    asm("cvt.rna.tf32.f32 %0, %1;" : "=r"(u) : "f"(x));
    return __uint_as_float(u);
}
__device__ __forceinline__ float2 split2(float v) {
    float h = tf32r(v);
    return make_float2(h, tf32r(v - h));
}
#define U32F(f) __float_as_uint(f)

__device__ __forceinline__ void mma8(float4& d, const uint32_t a[4],
                                     uint32_t b0, uint32_t b1) {
    asm volatile(
        "mma.sync.aligned.m16n8k8.row.col.f32.tf32.tf32.f32 "
        "{%0,%1,%2,%3},{%4,%5,%6,%7},{%8,%9},{%0,%1,%2,%3};"
        : "+f"(d.x), "+f"(d.y), "+f"(d.z), "+f"(d.w)
        : "r"(a[0]), "r"(a[1]), "r"(a[2]), "r"(a[3]), "r"(b0), "r"(b1));
}

__device__ __forceinline__ void cpa16(uint32_t dst, const void* src) {
    asm volatile("cp.async.ca.shared.global [%0], [%1], 16;" :: "r"(dst), "l"(src));
}
__device__ __forceinline__ void cpa16z(uint32_t dst, const void* src, int sz) {
    asm volatile("cp.async.ca.shared.global [%0], [%1], 16, %2;"
                 :: "r"(dst), "l"(src), "r"(sz));
}
#define CPA_COMMIT() asm volatile("cp.async.commit_group;" ::: "memory")
#define CPA_WAIT(n)  asm volatile("cp.async.wait_group %0;" :: "n"(n) : "memory")

// ---------------- deterministic CSR of base graph ----------------
__global__ void build_csr_kernel(const int* __restrict__ edge) {
    const int* dst = edge + EE;
    int n = threadIdx.x;             // 0..127
    __shared__ int counts[NST];
    int cnt = 0;
    for (int e = 0; e < EE; e++) if (dst[e] == n) cnt++;
    counts[n] = cnt;
    __syncthreads();
    if (n == 0) {
        int s = 0;
        for (int i = 0; i < NST; i++) { d_csr_ptr[i] = s; s += counts[i]; }
        d_csr_ptr[NST] = s;
    }
    __syncthreads();
    int p = d_csr_ptr[n];
    for (int e = 0; e < EE; e++) if (dst[e] == n) d_csr_eid[p++] = e;  // stable
}

// ---------------- tf32 GEMM, double-buffered cp.async ----------------
// BM=128 BN=64 BK=16, 256 thr, warps 4x2, warp tile 32x32.
// SPLIT: 1 = 2-term B split (B float2 hi/lo), 0 = single tf32 (B float, pre-rounded)
// EPI: 0 = +bias, 1 = +bias+station+horizon, 3 = conv fused (relu, h+=, skip+=)
// AMODE: 0 = plain A, 1 = conv gather (dil), 2 = A + A2
template<int EPI, int AMODE, int SPLIT>
__global__ void __launch_bounds__(256, 3) gemm_tc(
    const float* __restrict__ A, const float* __restrict__ A2,
    const void* __restrict__ Bv, const float* __restrict__ bias,
    float* __restrict__ C, int N, int Kd, int dil, int first,
    float* __restrict__ skipb,
    const float* __restrict__ aux1, const float* __restrict__ aux2)
{
    __shared__ float As[2][128][20];
    __shared__ float Bs[2][16][136];

    int tid = threadIdx.x, lane = tid & 31, w = tid >> 5;
    int bm = blockIdx.y << 7, bn = blockIdx.x << 6;
    int wm = w >> 1, wn = w & 1;
    int r = lane >> 2, cg = lane & 3;

    float4 acc[2][4];
#pragma unroll
    for (int mt = 0; mt < 2; mt++)
#pragma unroll
        for (int nt = 0; nt < 4; nt++) acc[mt][nt] = make_float4(0.f, 0.f, 0.f, 0.f);

    int arow = tid >> 2, akq = (tid & 3) << 2;
    int KT = Kd >> 4;

    auto loadA = [&](int kt, int st) {
        int k0 = kt << 4;
#pragma unroll
        for (int i = 0; i < 2; i++) {
            int m = arow + (i << 6);
            uint32_t dst = (uint32_t)__cvta_generic_to_shared(&As[st][m][akq]);
            if (AMODE == 1) {
                int kg = k0 + akq;
                int tap = kg >> 8;
                int shift = (2 - tap) * dil;
                int node = bm + m;
                int t = (node >> 7) % TT;
                bool ok = (t >= shift);
                const float* src = ok ? (A + (size_t)(node - (shift << 7)) * CC + (kg & 255)) : A;
                cpa16z(dst, src, ok ? 16 : 0);
            } else if (AMODE == 2) {
                size_t off = (size_t)(bm + m) * Kd + k0 + akq;
                float4 a = *(const float4*)(A + off);
                float4 b = *(const float4*)(A2 + off);
                *(float4*)&As[st][m][akq] =
                    make_float4(a.x + b.x, a.y + b.y, a.z + b.z, a.w + b.w);
            } else {
                cpa16(dst, A + (size_t)(bm + m) * Kd + k0 + akq);
            }
        }
    };
    auto loadB = [&](int kt, int st) {
        int k0 = kt << 4;
        if (SPLIT) {
            const float2* B = (const float2*)Bv;
#pragma unroll
            for (int i = 0; i < 2; i++) {
                int idx = tid + (i << 8);
                int kr = idx >> 5, c2 = (idx & 31) << 1;        // float2 col
                uint32_t dst = (uint32_t)__cvta_generic_to_shared(&Bs[st][kr][c2 << 1]);
                cpa16(dst, B + (size_t)(k0 + kr) * N + bn + c2);
            }
        } else {
            const float* B = (const float*)Bv;
            int kr = tid >> 4, nc = (tid & 15) << 2;
            uint32_t dst = (uint32_t)__cvta_generic_to_shared(&Bs[st][kr][nc]);
            cpa16(dst, B + (size_t)(k0 + kr) * N + bn + nc);
        }
    };

    loadA(0, 0); loadB(0, 0);
    CPA_COMMIT();

    for (int kt = 0; kt < KT; kt++) {
        int st = kt & 1;
        if (kt + 1 < KT) {
            loadA(kt + 1, st ^ 1); loadB(kt + 1, st ^ 1);
            CPA_COMMIT();
            CPA_WAIT(1);
        } else {
            CPA_WAIT(0);
        }
        __syncthreads();
#pragma unroll
        for (int kk = 0; kk < 16; kk += 8) {
            uint32_t ah[2][4];
#pragma unroll
            for (int mt = 0; mt < 2; mt++) {
                int m = (wm << 5) + (mt << 4) + r;
                ah[mt][0] = U32F(tf32r(As[st][m][kk+cg]));
                ah[mt][1] = U32F(tf32r(As[st][m+8][kk+cg]));
                ah[mt][2] = U32F(tf32r(As[st][m][kk+cg+4]));
                ah[mt][3] = U32F(tf32r(As[st][m+8][kk+cg+4]));
            }
#pragma unroll
            for (int nt = 0; nt < 4; nt++) {
                int n = (wn << 5) + (nt << 3) + r;
                if (SPLIT) {
                    float2 b0 = ((const float2*)&Bs[st][kk+cg  ][0])[n];
                    float2 b1 = ((const float2*)&Bs[st][kk+cg+4][0])[n];
#pragma unroll
                    for (int mt = 0; mt < 2; mt++) {
                        mma8(acc[mt][nt], ah[mt], U32F(b0.x), U32F(b1.x));
                        mma8(acc[mt][nt], ah[mt], U32F(b0.y), U32F(b1.y));
                    }
                } else {
                    uint32_t b0 = U32F(Bs[st][kk+cg  ][n]);
                    uint32_t b1 = U32F(Bs[st][kk+cg+4][n]);
#pragma unroll
                    for (int mt = 0; mt < 2; mt++)
                        mma8(acc[mt][nt], ah[mt], b0, b1);
                }
            }
        }
        __syncthreads();
    }

    // ---- epilogue ----
#pragma unroll
    for (int mt = 0; mt < 2; mt++) {
        int m0 = bm + (wm << 5) + (mt << 4) + r;
        int m1 = m0 + 8;
#pragma unroll
        for (int nt = 0; nt < 4; nt++) {
            int col = bn + (wn << 5) + (nt << 3) + (cg << 1);
            float b0 = bias ? bias[col] : 0.f;
            float b1 = bias ? bias[col+1] : 0.f;
            float2 v0 = make_float2(acc[mt][nt].x + b0, acc[mt][nt].y + b1);
            float2 v1 = make_float2(acc[mt][nt].z + b0, acc[mt][nt].w + b1);
            if (EPI == 1) {
                int s0 = (m0 & 127) * CC + col, t0 = ((m0 >> 7) % TT) * CC + col;
                int s1 = (m1 & 127) * CC + col, t1 = ((m1 >> 7) % TT) * CC + col;
                v0.x += aux1[s0] + aux2[t0];     v0.y += aux1[s0+1] + aux2[t0+1];
                v1.x += aux1[s1] + aux2[t1];     v1.y += aux1[s1+1] + aux2[t1+1];
            }
            if (EPI == 3) {
                v0.x = fmaxf(v0.x, 0.f); v0.y = fmaxf(v0.y, 0.f);
                v1.x = fmaxf(v1.x, 0.f); v1.y = fmaxf(v1.y, 0.f);
                size_t o0 = (size_t)m0 * CC + col, o1 = (size_t)m1 * CC + col;
                float2 h0 = *(const float2*)(A + o0);
                float2 h1 = *(const float2*)(A + o1);
                *(float2*)(C + o0) = make_float2(h0.x + v0.x, h0.y + v0.y);
                *(float2*)(C + o1) = make_float2(h1.x + v1.x, h1.y + v1.y);
                float2 s0, s1;
                if (first) { s0 = v0; s1 = v1; }
                else {
                    float2 p0 = *(const float2*)(skipb + o0);
                    float2 p1 = *(const float2*)(skipb + o1);
                    s0 = make_float2(p0.x + v0.x, p0.y + v0.y);
                    s1 = make_float2(p1.x + v1.x, p1.y + v1.y);
                }
                *(float2*)(skipb + o0) = s0;
                *(float2*)(skipb + o1) = s1;
            } else {
                *(float2*)(C + (size_t)m0 * N + col) = v0;
                *(float2*)(C + (size_t)m1 * N + col) = v1;
            }
        }
    }
}

// ---------------- weight prep ----------------
__global__ void transpose_w_all(const float* __restrict__ w, float2* __restrict__ wt) {
    int idx = blockIdx.x * 256 + threadIdx.x;        // < 3*3*256*256
    int l = idx / (KK*CC*CC);
    int rem = idx - l * (KK*CC*CC);
    int tap = rem >> 16;
    int cin = (rem >> 8) & 255;
    int cout = rem & 255;
    wt[idx] = split2(w[(((size_t)l*CC + cout)*CC + cin)*KK + tap]);
}

__global__ void pack_qkv_kernel(const float* __restrict__ Wq, const float* __restrict__ Wk,
                                const float* __restrict__ Wv, const float* __restrict__ bq,
                                const float* __restrict__ bk, const float* __restrict__ bv,
                                float* __restrict__ W, float* __restrict__ b) {
    int idx = blockIdx.x * 256 + threadIdx.x;        // < 256*768
    int k = idx / 768, n = idx - k * 768;
    int sel = n >> 8, nn = n & 255;
    const float* src = sel == 0 ? Wq : (sel == 1 ? Wk : Wv);
    W[idx] = tf32r(src[k * CC + nn]);
    if (idx < 768) {
        const float* bs = sel == 0 ? bq : (sel == 1 ? bk : bv);
        b[idx] = bs[nn];
    }
}

__global__ void pack_wlr_kernel(const float* __restrict__ wl, const float* __restrict__ wr,
                                float* __restrict__ W) {
    int idx = blockIdx.x * 256 + threadIdx.x;        // < 3*256*1024
    int l = idx >> 18;
    int rem = idx & 262143;
    int k = rem >> 10, n = rem & 1023;
    float v = (n < 512) ? wl[(size_t)l*CC*512 + k*512 + n]
                        : wr[(size_t)l*CC*512 + k*512 + (n - 512)];
    W[idx] = tf32r(v);
}

// enc | skip | wo | gate, tf32-rounded, one launch
__global__ void prep_small(const float* __restrict__ enc, const float* __restrict__ skp,
                           const float* __restrict__ wo, const float* __restrict__ gate,
                           float* __restrict__ o) {
    int i = blockIdx.x * 256 + threadIdx.x;   // < 163840
    float v;
    if (i < 16384)        v = enc[i];
    else if (i < 32768)   v = skp[i - 16384];
    else if (i < 98304)   v = wo[i - 32768];
    else                  v = gate[i - 98304];
    o[i] = tf32r(v);
}

// ---------------- fused GAT with smem edge cache ----------------
#define GAT_SMEM ((1024 + ECAP*512) * 4)
__global__ void __launch_bounds__(256) gat_fused_kernel(
    const int* __restrict__ edge, const float* __restrict__ xlr,
    const float* __restrict__ att,
    const float* __restrict__ gatb, const float* __restrict__ gamma,
    const float* __restrict__ beta, float* __restrict__ h)
{
    extern __shared__ float gsm[];
    float* xr_sh  = gsm;            // 512
    float* att_sh = gsm + 512;      // 512 (reused as LN reduce buffer)
    float* xe     = gsm + 1024;     // ECAP * 512

    __shared__ float2 logit_sh[MAXE];
    __shared__ float sh_m[2], sh_d[2], sw0[MAXE], sw1[MAXE];
    __shared__ int s_si[MAXE];

    int i = blockIdx.x;
    int tid = threadIdx.x, lane = tid & 31, w = tid >> 5;
    int g = i >> 7, n = i & 127;
    int p0 = d_csr_ptr[n], p1 = d_csr_ptr[n+1];
    int nE = p1 - p0 + 1;     // + self loop (j=0)

    xr_sh[tid]       = xlr[(size_t)i*1024 + 512 + tid];
    xr_sh[256 + tid] = xlr[(size_t)i*1024 + 768 + tid];
    att_sh[tid]       = att[tid];
    att_sh[256 + tid] = att[256 + tid];
    if (tid < nE)
        s_si[tid] = (tid == 0) ? i : ((g << 7) + edge[d_csr_eid[p0 + tid - 1]]);
    __syncthreads();

    // phase A: per-edge logits (warp per edge), caching xl rows in smem
    for (int j = w; j < nE; j += 8) {
        const float* px = xlr + (size_t)s_si[j] * 1024;
        float* xc = xe + j * 512;
        float s0 = 0.f, s1 = 0.f;
        for (int c = lane; c < 256; c += 32) {
            float x0 = px[c], x1 = px[256 + c];
            if (j < ECAP) { xc[c] = x0; xc[256 + c] = x1; }
            float v0 = x0 + xr_sh[c];
            v0 = v0 > 0.f ? v0 : 0.2f * v0;
            s0 = fmaf(att_sh[c], v0, s0);
            float v1 = x1 + xr_sh[256 + c];
            v1 = v1 > 0.f ? v1 : 0.2f * v1;
            s1 = fmaf(att_sh[256 + c], v1, s1);
        }
#pragma unroll
        for (int o = 16; o; o >>= 1) {
            s0 += __shfl_xor_sync(0xffffffffu, s0, o);
            s1 += __shfl_xor_sync(0xffffffffu, s1, o);
        }
        if (lane == 0) logit_sh[j] = make_float2(s0, s1);
    }
    __syncthreads();

    // phase B: per-head max + denom (warp per head)
    if (w < 2) {
        float m = -1e30f;
        for (int j = lane; j < nE; j += 32) {
            float lv = (w == 0) ? logit_sh[j].x : logit_sh[j].y;
            m = fmaxf(m, lv);
        }
#pragma unroll
        for (int o = 16; o; o >>= 1) m = fmaxf(m, __shfl_xor_sync(0xffffffffu, m, o));
        float den = 0.f;
        for (int j = lane; j < nE; j += 32) {
            float lv = (w == 0) ? logit_sh[j].x : logit_sh[j].y;
            den += expf(lv - m);
        }
#pragma unroll
        for (int o = 16; o; o >>= 1) den += __shfl_xor_sync(0xffffffffu, den, o);
        if (lane == 0) { sh_m[w] = m; sh_d[w] = den; }
    }
    __syncthreads();
    if (tid < nE) {
        sw0[tid] = expf(logit_sh[tid].x - sh_m[0]);
        sw1[tid] = expf(logit_sh[tid].y - sh_m[1]);
    }
    __syncthreads();

    // phase C: weighted aggregation from smem cache
    int c = tid;
    float acc0 = 0.f, acc1 = 0.f;
    for (int j = 0; j < nE; j++) {
        const float* xp = (j < ECAP) ? (xe + j * 512)
                                     : (xlr + (size_t)s_si[j] * 1024);
        acc0 = fmaf(sw0[j], xp[c], acc0);
        acc1 = fmaf(sw1[j], xp[256 + c], acc1);
    }
    float hg = 0.5f * (acc0 / (sh_d[0] + 1e-16f) + acc1 / (sh_d[1] + 1e-16f)) + gatb[c];
    float v = h[(size_t)i*CC + c] + hg;

    float* sred = att_sh;
    sred[c] = v; __syncthreads();
#pragma unroll
    for (int s = 128; s; s >>= 1) { if (c < s) sred[c] += sred[c + s]; __syncthreads(); }
    float mean = sred[0] * (1.f/256.f); __syncthreads();
    float d = v - mean;
    sred[c] = d * d; __syncthreads();
#pragma unroll
    for (int s = 128; s; s >>= 1) { if (c < s) sred[c] += sred[c + s]; __syncthreads(); }
    float var = sred[0] * (1.f/256.f);
    h[(size_t)i*CC + c] = d * rsqrtf(var + 1e-5f) * gamma[c] + beta[c];
}

// ---------------- MHA: block per (head, bt), smem-staged K^T and V ----------
#define MHA_SMEM ((64*132 + 128*68 + 8*64 + 8*128) * 4)
__global__ void __launch_bounds__(256) mha_kernel(const float* __restrict__ qkv,
                                                  float* __restrict__ aoh) {
    extern __shared__ float sm[];
    float* sKT = sm;                  // [64][132]
    float* sV  = sm + 64*132;         // [128][68]
    float* sQ  = sV + 128*68;         // [8][64]
    float* sP  = sQ + 8*64;           // [8][128]

    int head = blockIdx.x, bt = blockIdx.y;
    int base = bt << 7;
    int off = head << 6;
    int tid = threadIdx.x, lane = tid & 31, w = tid >> 5;

    for (int idx = tid; idx < 128*64; idx += 256) {
        int j = idx >> 6, d = idx & 63;
        sKT[d*132 + j] = qkv[(size_t)(base + j)*768 + 256 + off + d];
    }
    for (int idx = tid; idx < 128*16; idx += 256) {
        int j = idx >> 4, d4 = (idx & 15) << 2;
        float4 v = *(const float4*)(qkv + (size_t)(base + j)*768 + 512 + off + d4);
        *(float4*)(sV + j*68 + d4) = v;
    }
    __syncthreads();

    for (int it = 0; it < 16; it++) {
        int q = (it << 3) + w;
        sQ[w*64 + lane]      = qkv[(size_t)(base + q)*768 + off + lane];
        sQ[w*64 + 32 + lane] = qkv[(size_t)(base + q)*768 + off + 32 + lane];
        __syncwarp();
        float s0 = 0.f, s1 = 0.f, s2 = 0.f, s3 = 0.f;
#pragma unroll 8
        for (int d = 0; d < 64; d++) {
            float qd = sQ[w*64 + d];
            const float* kr = sKT + d*132;
            s0 = fmaf(qd, kr[lane], s0);
            s1 = fmaf(qd, kr[32 + lane], s1);
            s2 = fmaf(qd, kr[64 + lane], s2);
            s3 = fmaf(qd, kr[96 + lane], s3);
        }
        s0 *= 0.125f; s1 *= 0.125f; s2 *= 0.125f; s3 *= 0.125f;
        float m = fmaxf(fmaxf(s0, s1), fmaxf(s2, s3));
#pragma unroll
        for (int o = 16; o; o >>= 1) m = fmaxf(m, __shfl_xor_sync(0xffffffffu, m, o));
        float e0 = expf(s0 - m), e1 = expf(s1 - m), e2 = expf(s2 - m), e3 = expf(s3 - m);
        float den = e0 + e1 + e2 + e3;
#pragma unroll
        for (int o = 16; o; o >>= 1) den += __shfl_xor_sync(0xffffffffu, den, o);
        float inv = 1.f / den;
        sP[w*128 + lane]      = e0 * inv;
        sP[w*128 + 32 + lane] = e1 * inv;
        sP[w*128 + 64 + lane] = e2 * inv;
        sP[w*128 + 96 + lane] = e3 * inv;
        __syncwarp();
        float o0 = 0.f, o1 = 0.f;
#pragma unroll 4
        for (int j = 0; j < 128; j++) {
            float pw = sP[w*128 + j];
            o0 = fmaf(pw, sV[j*68 + lane], o0);
            o1 = fmaf(pw, sV[j*68 + 32 + lane], o1);
        }
        aoh[(size_t)(base + q)*CC + off + lane]      = o0;
        aoh[(size_t)(base + q)*CC + off + 32 + lane] = o1;
        __syncwarp();
    }
}

// ---------------- residual(skip+h+ao) + LayerNorm ----------------
__global__ void __launch_bounds__(256) resid_ln_kernel(const float* __restrict__ skip,
                                                       const float* __restrict__ h,
                                                       const float* __restrict__ ao,
                                                       const float* __restrict__ gamma,
                                                       const float* __restrict__ beta,
                                                       float* __restrict__ out) {
    int i = blockIdx.x;
    int c = threadIdx.x;
    size_t o = (size_t)i*CC + c;
    float v = skip[o] + h[o] + ao[o];
    __shared__ float sred[256];
    sred[c] = v; __syncthreads();
#pragma unroll
    for (int s = 128; s; s >>= 1) { if (c < s) sred[c] += sred[c + s]; __syncthreads(); }
    float mean = sred[0] * (1.f/256.f); __syncthreads();
    float d = v - mean;
    sred[c] = d * d; __syncthreads();
#pragma unroll
    for (int s = 128; s; s >>= 1) { if (c < s) sred[c] += sred[c + s]; __syncthreads(); }
    float var = sred[0] * (1.f/256.f);
    out[o] = d * rsqrtf(var + 1e-5f) * gamma[c] + beta[c];
}

// ---------------- gate + skip + output head + softplus ----------------
__global__ void __launch_bounds__(256) final_kernel(const float* __restrict__ gpre,
                                                    const float* __restrict__ href,
                                                    const float* __restrict__ skip2,
                                                    const float* __restrict__ W_out,
                                                    const float* __restrict__ b_out,
                                                    float* __restrict__ out) {
    int i = blockIdx.x;
    int c = threadIdx.x;
    float g = 1.f / (1.f + expf(-gpre[(size_t)i*CC + c]));
    float hf = g * href[(size_t)i*CC + c] + (1.f - g) * skip2[(size_t)i*CC + c];
    __shared__ float r0[256], r1[256];
    r0[c] = hf * W_out[c*2 + 0];
    r1[c] = hf * W_out[c*2 + 1];
    __syncthreads();
#pragma unroll
    for (int s = 128; s; s >>= 1) {
        if (c < s) { r0[c] += r0[c + s]; r1[c] += r1[c + s]; }
        __syncthreads();
    }
    if (c == 0) {
        float o0 = r0[0] + b_out[0];
        float o1 = r1[0] + b_out[1];
        out[(size_t)i*2 + 0] = o0;
        out[(size_t)i*2 + 1] = fmaxf(o1, 0.f) + log1pf(expf(-fabsf(o1)));
    }
}

// ---------------- host orchestration ----------------
extern "C" void kernel_launch(void* const* d_in, const int* in_sizes, int n_in,
                              void* d_out, int out_size) {
    const float* x        = (const float*)d_in[0];
    const int*   edge     = (const int*)  d_in[1];
    const float* W_enc    = (const float*)d_in[2];
    const float* b_enc    = (const float*)d_in[3];
    const float* station  = (const float*)d_in[4];
    const float* horizon  = (const float*)d_in[5];
    const float* conv_w   = (const float*)d_in[6];
    const float* conv_b   = (const float*)d_in[7];
    const float* gat_wl   = (const float*)d_in[8];
    const float* gat_wr   = (const float*)d_in[9];
    const float* gat_att  = (const float*)d_in[10];
    const float* gat_b    = (const float*)d_in[11];
    const float* norm_g   = (const float*)d_in[12];
    const float* norm_b   = (const float*)d_in[13];
    const float* Wq       = (const float*)d_in[14];
    const float* Wk       = (const float*)d_in[15];
    const float* Wv       = (const float*)d_in[16];
    const float* Wo       = (const float*)d_in[17];
    const float* bq       = (const float*)d_in[18];
    const float* bk       = (const float*)d_in[19];
    const float* bv       = (const float*)d_in[20];
    const float* bo       = (const float*)d_in[21];
    const float* an_g     = (const float*)d_in[22];
    const float* an_b     = (const float*)d_in[23];
    const float* W_skip   = (const float*)d_in[24];
    const float* b_skip   = (const float*)d_in[25];
    const float* W_gate   = (const float*)d_in[26];
    const float* b_gate   = (const float*)d_in[27];
    const float* W_out    = (const float*)d_in[28];
    const float* b_out    = (const float*)d_in[29];
    float* out = (float*)d_out;

    float* buf = nullptr;
    cudaGetSymbolAddress((void**)&buf, d_buf);
    float2* wbuf2 = nullptr;
    cudaGetSymbolAddress((void**)&wbuf2, d_wbuf2);
    float* wbuf1 = nullptr;
    cudaGetSymbolAddress((void**)&wbuf1, d_wbuf1);

    float* g_h    = buf + OFF_H;
    float* g_h2   = buf + OFF_H2;
    float* g_skip = buf + OFF_SKIP;
    float* g_y    = buf + OFF_Y;
    float* g_xlr  = buf + OFF_XLR;
    float* g_qkv  = buf + OFF_QKV;
    float* g_ao   = buf + OFF_AO;
    float* g_href = buf + OFF_HREF;
    float* g_bqkv = buf + OFF_BQKV;

    float* w_wlr  = wbuf1 + WF_WLR;
    float* w_qkv  = wbuf1 + WF_QKV;
    float* w_enc  = wbuf1 + WF_ENC;
    float* w_skip = wbuf1 + WF_SKIP;
    float* w_wo   = wbuf1 + WF_WO;
    float* w_gate = wbuf1 + WF_GATE;

    const dim3 thr(256);
    const dim3 gN256(CC/64, NNODE/128);           // (4, 96)
    const dim3 gN768(768/64, NNODE/128);          // (12, 96)
    const dim3 gN1024(1024/64, NNODE/128);        // (16, 96)

    cudaFuncSetAttribute(mha_kernel, cudaFuncAttributeMaxDynamicSharedMemorySize, MHA_SMEM);
    cudaFuncSetAttribute(gat_fused_kernel, cudaFuncAttributeMaxDynamicSharedMemorySize,
                         GAT_SMEM);

    build_csr_kernel<<<1, NST>>>(edge);
    transpose_w_all<<<(LL*KK*CC*CC)/256, thr>>>(conv_w, wbuf2);
    pack_qkv_kernel<<<(CC*768)/256, thr>>>(Wq, Wk, Wv, bq, bk, bv, w_qkv, g_bqkv);
    pack_wlr_kernel<<<(LL*CC*1024)/256, thr>>>(gat_wl, gat_wr, w_wlr);
    prep_small<<<163840/256, thr>>>(W_enc, W_skip, Wo, W_gate, w_enc);

    // encoder: h = x @ W_enc + b_enc + station + horizon
    gemm_tc<1,0,0><<<gN256, thr>>>(x, nullptr, w_enc, b_enc, g_h, CC, FINF, 0, 0,
                                   nullptr, station, horizon);

    float* hcur = g_h;
    float* hnext = g_h2;
    for (int l = 0; l < LL; l++) {
        int dil = 1 << l;
        gemm_tc<3,1,1><<<gN256, thr>>>(hcur, nullptr, wbuf2 + (size_t)l*KK*CC*CC,
                                       conv_b + l*CC, hnext, CC, KK*CC, dil, l == 0,
                                       g_skip, nullptr, nullptr);
        gemm_tc<0,0,0><<<gN1024, thr>>>(hnext, nullptr, w_wlr + (size_t)l*CC*1024, nullptr,
                                        g_xlr, 1024, CC, 0, 0, nullptr, nullptr, nullptr);
        gat_fused_kernel<<<NNODE, thr, GAT_SMEM>>>(edge, g_xlr, gat_att + l*GHH*CC,
                                                   gat_b + l*CC, norm_g + l*CC,
                                                   norm_b + l*CC, hnext);
        float* tmp = hcur; hcur = hnext; hnext = tmp;
    }

    // QKV in one GEMM, A = skip + h (fused)
    gemm_tc<0,2,0><<<gN768, thr>>>(g_skip, hcur, w_qkv, g_bqkv, g_qkv, 768, CC, 0, 0,
                                   nullptr, nullptr, nullptr);
    mha_kernel<<<dim3(NHH, NG), thr, MHA_SMEM>>>(g_qkv, g_xlr);
    gemm_tc<0,0,0><<<gN256, thr>>>(g_xlr, nullptr, w_wo, bo, g_ao, CC, CC, 0, 0,
                                   nullptr, nullptr, nullptr);
    resid_ln_kernel<<<NNODE, thr>>>(g_skip, hcur, g_ao, an_g, an_b, g_href);

    // gate + skip branch + output head
    gemm_tc<0,0,0><<<gN256, thr>>>(x, nullptr, w_skip, b_skip, g_y, CC, FINF, 0, 0,
                                   nullptr, nullptr, nullptr);
    gemm_tc<0,0,0><<<gN256, thr>>>(g_href, nullptr, w_gate, b_gate, g_qkv, CC, CC, 0, 0,
                                   nullptr, nullptr, nullptr);
    final_kernel<<<NNODE, thr>>>(g_qkv, g_href, g_y, W_out, b_out, out);

    (void)in_sizes; (void)n_in; (void)out_size;
}

// round 7
// speedup vs baseline: 2.9751x; 1.0051x over previous
#include <cuda_runtime.h>
#include <math.h>
#include <stdint.h>

// ---------------- problem constants ----------------
#define BBATCH 4
#define TT     24
#define NST    128
#define FINF   64
#define CC     256
#define LL     3
#define KK     3
#define GHH    2
#define NHH    4
#define EE     1024
#define NG     (BBATCH*TT)        // 96
#define NNODE  (NG*NST)           // 12288
#define MAXE   64                 // max in-degree bound (mean 8)
#define ECAP   24                 // smem-cached edges per node

// ---------------- static scratch ----------------
__device__ int d_csr_ptr[NST+1];
__device__ int d_csr_eid[EE];

#define OFF_H    ((size_t)0)
#define OFF_H2   (OFF_H    + (size_t)NNODE*CC)
#define OFF_SKIP (OFF_H2   + (size_t)NNODE*CC)
#define OFF_Y    (OFF_SKIP + (size_t)NNODE*CC)
#define OFF_XLR  (OFF_Y    + (size_t)NNODE*CC)
#define OFF_QKV  (OFF_XLR  + (size_t)NNODE*1024)
#define OFF_AO   (OFF_QKV  + (size_t)NNODE*768)
#define OFF_HREF (OFF_AO   + (size_t)NNODE*CC)
#define OFF_BQKV (OFF_HREF + (size_t)NNODE*CC)
#define TOTF     (OFF_BQKV + (size_t)768)
__device__ float d_buf[TOTF];

// conv weights: pre-split (hi,lo) float2
__device__ float2 d_wbuf2[(size_t)LL*KK*CC*CC];
// all other weights: tf32-rounded float
#define WF_WLR  ((size_t)0)                        // 3*256*1024
#define WF_QKV  (WF_WLR  + (size_t)LL*CC*1024)     // 256*768
#define WF_ENC  (WF_QKV  + (size_t)CC*768)         // 64*256
#define WF_SKIP (WF_ENC  + (size_t)FINF*CC)
#define WF_WO   (WF_SKIP + (size_t)FINF*CC)        // 256*256
#define WF_GATE (WF_WO   + (size_t)CC*CC)
#define TOTWF   (WF_GATE + (size_t)CC*CC)
__device__ float d_wbuf1[TOTWF];

// ---------------- helpers ----------------
__device__ __forceinline__ float tf32r(float x) {
    uint32_t u;
    asm("cvt.rna.tf32.f32 %0, %1;" : "=r"(u) : "f"(x));
    return __uint_as_float(u);
}
__device__ __forceinline__ float2 split2(float v) {
    float h = tf32r(v);
    return make_float2(h, tf32r(v - h));
}
#define U32F(f) __float_as_uint(f)

__device__ __forceinline__ void mma8(float4& d, const uint32_t a[4],
                                     uint32_t b0, uint32_t b1) {
    asm volatile(
        "mma.sync.aligned.m16n8k8.row.col.f32.tf32.tf32.f32 "
        "{%0,%1,%2,%3},{%4,%5,%6,%7},{%8,%9},{%0,%1,%2,%3};"
        : "+f"(d.x), "+f"(d.y), "+f"(d.z), "+f"(d.w)
        : "r"(a[0]), "r"(a[1]), "r"(a[2]), "r"(a[3]), "r"(b0), "r"(b1));
}

__device__ __forceinline__ void cpa16(uint32_t dst, const void* src) {
    asm volatile("cp.async.ca.shared.global [%0], [%1], 16;" :: "r"(dst), "l"(src));
}
__device__ __forceinline__ void cpa16z(uint32_t dst, const void* src, int sz) {
    asm volatile("cp.async.ca.shared.global [%0], [%1], 16, %2;"
                 :: "r"(dst), "l"(src), "r"(sz));
}
#define CPA_COMMIT() asm volatile("cp.async.commit_group;" ::: "memory")
#define CPA_WAIT(n)  asm volatile("cp.async.wait_group %0;" :: "n"(n) : "memory")

// ---------------- deterministic CSR of base graph ----------------
__global__ void build_csr_kernel(const int* __restrict__ edge) {
    const int* dst = edge + EE;
    int n = threadIdx.x;             // 0..127
    __shared__ int counts[NST];
    int cnt = 0;
    for (int e = 0; e < EE; e++) if (dst[e] == n) cnt++;
    counts[n] = cnt;
    __syncthreads();
    if (n == 0) {
        int s = 0;
        for (int i = 0; i < NST; i++) { d_csr_ptr[i] = s; s += counts[i]; }
        d_csr_ptr[NST] = s;
    }
    __syncthreads();
    int p = d_csr_ptr[n];
    for (int e = 0; e < EE; e++) if (dst[e] == n) d_csr_eid[p++] = e;  // stable
}

// ---------------- tf32 GEMM, double-buffered cp.async ----------------
// BM=128 BN=64 BK=16, 256 thr, warps 4x2, warp tile 32x32.
// SPLIT: 1 = 2-term B split (B float2 hi/lo), 0 = single tf32 (pre-rounded B)
// ACVT : 1 = RNA-round A fragments (accuracy-critical conv), 0 = raw fp32 bits
// EPI: 0 = +bias, 1 = +bias+station+horizon, 3 = conv fused (relu, h+=, skip+=)
// AMODE: 0 = plain A, 1 = conv gather (dil), 2 = A + A2
template<int EPI, int AMODE, int SPLIT, int ACVT>
__global__ void __launch_bounds__(256, 3) gemm_tc(
    const float* __restrict__ A, const float* __restrict__ A2,
    const void* __restrict__ Bv, const float* __restrict__ bias,
    float* __restrict__ C, int N, int Kd, int dil, int first,
    float* __restrict__ skipb,
    const float* __restrict__ aux1, const float* __restrict__ aux2)
{
    __shared__ float As[2][128][20];
    __shared__ float Bs[2][16][136];

    int tid = threadIdx.x, lane = tid & 31, w = tid >> 5;
    int bm = blockIdx.y << 7, bn = blockIdx.x << 6;
    int wm = w >> 1, wn = w & 1;
    int r = lane >> 2, cg = lane & 3;

    float4 acc[2][4];
#pragma unroll
    for (int mt = 0; mt < 2; mt++)
#pragma unroll
        for (int nt = 0; nt < 4; nt++) acc[mt][nt] = make_float4(0.f, 0.f, 0.f, 0.f);

    int arow = tid >> 2, akq = (tid & 3) << 2;
    int KT = Kd >> 4;

    auto loadA = [&](int kt, int st) {
        int k0 = kt << 4;
#pragma unroll
        for (int i = 0; i < 2; i++) {
            int m = arow + (i << 6);
            uint32_t dst = (uint32_t)__cvta_generic_to_shared(&As[st][m][akq]);
            if (AMODE == 1) {
                int kg = k0 + akq;
                int tap = kg >> 8;
                int shift = (2 - tap) * dil;
                int node = bm + m;
                int t = (node >> 7) % TT;
                bool ok = (t >= shift);
                const float* src = ok ? (A + (size_t)(node - (shift << 7)) * CC + (kg & 255)) : A;
                cpa16z(dst, src, ok ? 16 : 0);
            } else if (AMODE == 2) {
                size_t off = (size_t)(bm + m) * Kd + k0 + akq;
                float4 a = *(const float4*)(A + off);
                float4 b = *(const float4*)(A2 + off);
                *(float4*)&As[st][m][akq] =
                    make_float4(a.x + b.x, a.y + b.y, a.z + b.z, a.w + b.w);
            } else {
                cpa16(dst, A + (size_t)(bm + m) * Kd + k0 + akq);
            }
        }
    };
    auto loadB = [&](int kt, int st) {
        int k0 = kt << 4;
        if (SPLIT) {
            const float2* B = (const float2*)Bv;
#pragma unroll
            for (int i = 0; i < 2; i++) {
                int idx = tid + (i << 8);
                int kr = idx >> 5, c2 = (idx & 31) << 1;
                uint32_t dst = (uint32_t)__cvta_generic_to_shared(&Bs[st][kr][c2 << 1]);
                cpa16(dst, B + (size_t)(k0 + kr) * N + bn + c2);
            }
        } else {
            const float* B = (const float*)Bv;
            int kr = tid >> 4, nc = (tid & 15) << 2;
            uint32_t dst = (uint32_t)__cvta_generic_to_shared(&Bs[st][kr][nc]);
            cpa16(dst, B + (size_t)(k0 + kr) * N + bn + nc);
        }
    };

    loadA(0, 0); loadB(0, 0);
    CPA_COMMIT();

    for (int kt = 0; kt < KT; kt++) {
        int st = kt & 1;
        if (kt + 1 < KT) {
            loadA(kt + 1, st ^ 1); loadB(kt + 1, st ^ 1);
            CPA_COMMIT();
            CPA_WAIT(1);
        } else {
            CPA_WAIT(0);
        }
        __syncthreads();
#pragma unroll
        for (int kk = 0; kk < 16; kk += 8) {
            uint32_t ah[2][4];
#pragma unroll
            for (int mt = 0; mt < 2; mt++) {
                int m = (wm << 5) + (mt << 4) + r;
                if (ACVT) {
                    ah[mt][0] = U32F(tf32r(As[st][m][kk+cg]));
                    ah[mt][1] = U32F(tf32r(As[st][m+8][kk+cg]));
                    ah[mt][2] = U32F(tf32r(As[st][m][kk+cg+4]));
                    ah[mt][3] = U32F(tf32r(As[st][m+8][kk+cg+4]));
                } else {
                    ah[mt][0] = U32F(As[st][m][kk+cg]);
                    ah[mt][1] = U32F(As[st][m+8][kk+cg]);
                    ah[mt][2] = U32F(As[st][m][kk+cg+4]);
                    ah[mt][3] = U32F(As[st][m+8][kk+cg+4]);
                }
            }
#pragma unroll
            for (int nt = 0; nt < 4; nt++) {
                int n = (wn << 5) + (nt << 3) + r;
                if (SPLIT) {
                    float2 b0 = ((const float2*)&Bs[st][kk+cg  ][0])[n];
                    float2 b1 = ((const float2*)&Bs[st][kk+cg+4][0])[n];
#pragma unroll
                    for (int mt = 0; mt < 2; mt++) {
                        mma8(acc[mt][nt], ah[mt], U32F(b0.x), U32F(b1.x));
                        mma8(acc[mt][nt], ah[mt], U32F(b0.y), U32F(b1.y));
                    }
                } else {
                    uint32_t b0 = U32F(Bs[st][kk+cg  ][n]);
                    uint32_t b1 = U32F(Bs[st][kk+cg+4][n]);
#pragma unroll
                    for (int mt = 0; mt < 2; mt++)
                        mma8(acc[mt][nt], ah[mt], b0, b1);
                }
            }
        }
        __syncthreads();
    }

    // ---- epilogue ----
#pragma unroll
    for (int mt = 0; mt < 2; mt++) {
        int m0 = bm + (wm << 5) + (mt << 4) + r;
        int m1 = m0 + 8;
#pragma unroll
        for (int nt = 0; nt < 4; nt++) {
            int col = bn + (wn << 5) + (nt << 3) + (cg << 1);
            float b0 = bias ? bias[col] : 0.f;
            float b1 = bias ? bias[col+1] : 0.f;
            float2 v0 = make_float2(acc[mt][nt].x + b0, acc[mt][nt].y + b1);
            float2 v1 = make_float2(acc[mt][nt].z + b0, acc[mt][nt].w + b1);
            if (EPI == 1) {
                int s0 = (m0 & 127) * CC + col, t0 = ((m0 >> 7) % TT) * CC + col;
                int s1 = (m1 & 127) * CC + col, t1 = ((m1 >> 7) % TT) * CC + col;
                v0.x += aux1[s0] + aux2[t0];     v0.y += aux1[s0+1] + aux2[t0+1];
                v1.x += aux1[s1] + aux2[t1];     v1.y += aux1[s1+1] + aux2[t1+1];
            }
            if (EPI == 3) {
                v0.x = fmaxf(v0.x, 0.f); v0.y = fmaxf(v0.y, 0.f);
                v1.x = fmaxf(v1.x, 0.f); v1.y = fmaxf(v1.y, 0.f);
                size_t o0 = (size_t)m0 * CC + col, o1 = (size_t)m1 * CC + col;
                float2 h0 = *(const float2*)(A + o0);
                float2 h1 = *(const float2*)(A + o1);
                *(float2*)(C + o0) = make_float2(h0.x + v0.x, h0.y + v0.y);
                *(float2*)(C + o1) = make_float2(h1.x + v1.x, h1.y + v1.y);
                float2 s0, s1;
                if (first) { s0 = v0; s1 = v1; }
                else {
                    float2 p0 = *(const float2*)(skipb + o0);
                    float2 p1 = *(const float2*)(skipb + o1);
                    s0 = make_float2(p0.x + v0.x, p0.y + v0.y);
                    s1 = make_float2(p1.x + v1.x, p1.y + v1.y);
                }
                *(float2*)(skipb + o0) = s0;
                *(float2*)(skipb + o1) = s1;
            } else {
                *(float2*)(C + (size_t)m0 * N + col) = v0;
                *(float2*)(C + (size_t)m1 * N + col) = v1;
            }
        }
    }
}

// ---------------- weight prep ----------------
__global__ void transpose_w_all(const float* __restrict__ w, float2* __restrict__ wt) {
    int idx = blockIdx.x * 256 + threadIdx.x;        // < 3*3*256*256
    int l = idx / (KK*CC*CC);
    int rem = idx - l * (KK*CC*CC);
    int tap = rem >> 16;
    int cin = (rem >> 8) & 255;
    int cout = rem & 255;
    wt[idx] = split2(w[(((size_t)l*CC + cout)*CC + cin)*KK + tap]);
}

__global__ void pack_qkv_kernel(const float* __restrict__ Wq, const float* __restrict__ Wk,
                                const float* __restrict__ Wv, const float* __restrict__ bq,
                                const float* __restrict__ bk, const float* __restrict__ bv,
                                float* __restrict__ W, float* __restrict__ b) {
    int idx = blockIdx.x * 256 + threadIdx.x;        // < 256*768
    int k = idx / 768, n = idx - k * 768;
    int sel = n >> 8, nn = n & 255;
    const float* src = sel == 0 ? Wq : (sel == 1 ? Wk : Wv);
    W[idx] = tf32r(src[k * CC + nn]);
    if (idx < 768) {
        const float* bs = sel == 0 ? bq : (sel == 1 ? bk : bv);
        b[idx] = bs[nn];
    }
}

__global__ void pack_wlr_kernel(const float* __restrict__ wl, const float* __restrict__ wr,
                                float* __restrict__ W) {
    int idx = blockIdx.x * 256 + threadIdx.x;        // < 3*256*1024
    int l = idx >> 18;
    int rem = idx & 262143;
    int k = rem >> 10, n = rem & 1023;
    float v = (n < 512) ? wl[(size_t)l*CC*512 + k*512 + n]
                        : wr[(size_t)l*CC*512 + k*512 + (n - 512)];
    W[idx] = tf32r(v);
}

// enc | skip | wo | gate, tf32-rounded, one launch
__global__ void prep_small(const float* __restrict__ enc, const float* __restrict__ skp,
                           const float* __restrict__ wo, const float* __restrict__ gate,
                           float* __restrict__ o) {
    int i = blockIdx.x * 256 + threadIdx.x;   // < 163840
    float v;
    if (i < 16384)        v = enc[i];
    else if (i < 32768)   v = skp[i - 16384];
    else if (i < 98304)   v = wo[i - 32768];
    else                  v = gate[i - 98304];
    o[i] = tf32r(v);
}

// ---------------- fused GAT with smem edge cache ----------------
#define GAT_SMEM ((1024 + ECAP*512) * 4)
__global__ void __launch_bounds__(256) gat_fused_kernel(
    const int* __restrict__ edge, const float* __restrict__ xlr,
    const float* __restrict__ att,
    const float* __restrict__ gatb, const float* __restrict__ gamma,
    const float* __restrict__ beta, float* __restrict__ h)
{
    extern __shared__ float gsm[];
    float* xr_sh  = gsm;            // 512
    float* att_sh = gsm + 512;      // 512 (reused as LN reduce buffer)
    float* xe     = gsm + 1024;     // ECAP * 512

    __shared__ float2 logit_sh[MAXE];
    __shared__ float sh_m[2], sh_d[2], sw0[MAXE], sw1[MAXE];
    __shared__ int s_si[MAXE];

    int i = blockIdx.x;
    int tid = threadIdx.x, lane = tid & 31, w = tid >> 5;
    int g = i >> 7, n = i & 127;
    int p0 = d_csr_ptr[n], p1 = d_csr_ptr[n+1];
    int nE = p1 - p0 + 1;     // + self loop (j=0)

    xr_sh[tid]       = xlr[(size_t)i*1024 + 512 + tid];
    xr_sh[256 + tid] = xlr[(size_t)i*1024 + 768 + tid];
    att_sh[tid]       = att[tid];
    att_sh[256 + tid] = att[256 + tid];
    if (tid < nE)
        s_si[tid] = (tid == 0) ? i : ((g << 7) + edge[d_csr_eid[p0 + tid - 1]]);
    __syncthreads();

    for (int j = w; j < nE; j += 8) {
        const float* px = xlr + (size_t)s_si[j] * 1024;
        float* xc = xe + j * 512;
        float s0 = 0.f, s1 = 0.f;
        for (int c = lane; c < 256; c += 32) {
            float x0 = px[c], x1 = px[256 + c];
            if (j < ECAP) { xc[c] = x0; xc[256 + c] = x1; }
            float v0 = x0 + xr_sh[c];
            v0 = v0 > 0.f ? v0 : 0.2f * v0;
            s0 = fmaf(att_sh[c], v0, s0);
            float v1 = x1 + xr_sh[256 + c];
            v1 = v1 > 0.f ? v1 : 0.2f * v1;
            s1 = fmaf(att_sh[256 + c], v1, s1);
        }
#pragma unroll
        for (int o = 16; o; o >>= 1) {
            s0 += __shfl_xor_sync(0xffffffffu, s0, o);
            s1 += __shfl_xor_sync(0xffffffffu, s1, o);
        }
        if (lane == 0) logit_sh[j] = make_float2(s0, s1);
    }
    __syncthreads();

    if (w < 2) {
        float m = -1e30f;
        for (int j = lane; j < nE; j += 32) {
            float lv = (w == 0) ? logit_sh[j].x : logit_sh[j].y;
            m = fmaxf(m, lv);
        }
#pragma unroll
        for (int o = 16; o; o >>= 1) m = fmaxf(m, __shfl_xor_sync(0xffffffffu, m, o));
        float den = 0.f;
        for (int j = lane; j < nE; j += 32) {
            float lv = (w == 0) ? logit_sh[j].x : logit_sh[j].y;
            den += expf(lv - m);
        }
#pragma unroll
        for (int o = 16; o; o >>= 1) den += __shfl_xor_sync(0xffffffffu, den, o);
        if (lane == 0) { sh_m[w] = m; sh_d[w] = den; }
    }
    __syncthreads();
    if (tid < nE) {
        sw0[tid] = expf(logit_sh[tid].x - sh_m[0]);
        sw1[tid] = expf(logit_sh[tid].y - sh_m[1]);
    }
    __syncthreads();

    int c = tid;
    float acc0 = 0.f, acc1 = 0.f;
    for (int j = 0; j < nE; j++) {
        const float* xp = (j < ECAP) ? (xe + j * 512)
                                     : (xlr + (size_t)s_si[j] * 1024);
        acc0 = fmaf(sw0[j], xp[c], acc0);
        acc1 = fmaf(sw1[j], xp[256 + c], acc1);
    }
    float hg = 0.5f * (acc0 / (sh_d[0] + 1e-16f) + acc1 / (sh_d[1] + 1e-16f)) + gatb[c];
    float v = h[(size_t)i*CC + c] + hg;

    float* sred = att_sh;
    sred[c] = v; __syncthreads();
#pragma unroll
    for (int s = 128; s; s >>= 1) { if (c < s) sred[c] += sred[c + s]; __syncthreads(); }
    float mean = sred[0] * (1.f/256.f); __syncthreads();
    float d = v - mean;
    sred[c] = d * d; __syncthreads();
#pragma unroll
    for (int s = 128; s; s >>= 1) { if (c < s) sred[c] += sred[c + s]; __syncthreads(); }
    float var = sred[0] * (1.f/256.f);
    h[(size_t)i*CC + c] = d * rsqrtf(var + 1e-5f) * gamma[c] + beta[c];
}

// ---------------- MHA: block per (head, bt), smem-staged K^T and V ----------
#define MHA_SMEM ((64*132 + 128*68 + 8*64 + 8*128) * 4)
__global__ void __launch_bounds__(256) mha_kernel(const float* __restrict__ qkv,
                                                  float* __restrict__ aoh) {
    extern __shared__ float sm[];
    float* sKT = sm;                  // [64][132]
    float* sV  = sm + 64*132;         // [128][68]
    float* sQ  = sV + 128*68;         // [8][64]
    float* sP  = sQ + 8*64;           // [8][128]

    int head = blockIdx.x, bt = blockIdx.y;
    int base = bt << 7;
    int off = head << 6;
    int tid = threadIdx.x, lane = tid & 31, w = tid >> 5;

    for (int idx = tid; idx < 128*64; idx += 256) {
        int j = idx >> 6, d = idx & 63;
        sKT[d*132 + j] = qkv[(size_t)(base + j)*768 + 256 + off + d];
    }
    for (int idx = tid; idx < 128*16; idx += 256) {
        int j = idx >> 4, d4 = (idx & 15) << 2;
        float4 v = *(const float4*)(qkv + (size_t)(base + j)*768 + 512 + off + d4);
        *(float4*)(sV + j*68 + d4) = v;
    }
    __syncthreads();

    for (int it = 0; it < 16; it++) {
        int q = (it << 3) + w;
        sQ[w*64 + lane]      = qkv[(size_t)(base + q)*768 + off + lane];
        sQ[w*64 + 32 + lane] = qkv[(size_t)(base + q)*768 + off + 32 + lane];
        __syncwarp();
        float s0 = 0.f, s1 = 0.f, s2 = 0.f, s3 = 0.f;
#pragma unroll 8
        for (int d = 0; d < 64; d++) {
            float qd = sQ[w*64 + d];
            const float* kr = sKT + d*132;
            s0 = fmaf(qd, kr[lane], s0);
            s1 = fmaf(qd, kr[32 + lane], s1);
            s2 = fmaf(qd, kr[64 + lane], s2);
            s3 = fmaf(qd, kr[96 + lane], s3);
        }
        s0 *= 0.125f; s1 *= 0.125f; s2 *= 0.125f; s3 *= 0.125f;
        float m = fmaxf(fmaxf(s0, s1), fmaxf(s2, s3));
#pragma unroll
        for (int o = 16; o; o >>= 1) m = fmaxf(m, __shfl_xor_sync(0xffffffffu, m, o));
        float e0 = expf(s0 - m), e1 = expf(s1 - m), e2 = expf(s2 - m), e3 = expf(s3 - m);
        float den = e0 + e1 + e2 + e3;
#pragma unroll
        for (int o = 16; o; o >>= 1) den += __shfl_xor_sync(0xffffffffu, den, o);
        float inv = 1.f / den;
        sP[w*128 + lane]      = e0 * inv;
        sP[w*128 + 32 + lane] = e1 * inv;
        sP[w*128 + 64 + lane] = e2 * inv;
        sP[w*128 + 96 + lane] = e3 * inv;
        __syncwarp();
        float o0 = 0.f, o1 = 0.f;
#pragma unroll 4
        for (int j = 0; j < 128; j++) {
            float pw = sP[w*128 + j];
            o0 = fmaf(pw, sV[j*68 + lane], o0);
            o1 = fmaf(pw, sV[j*68 + 32 + lane], o1);
        }
        aoh[(size_t)(base + q)*CC + off + lane]      = o0;
        aoh[(size_t)(base + q)*CC + off + 32 + lane] = o1;
        __syncwarp();
    }
}

// ---------------- residual(skip+h+ao) + LayerNorm ----------------
__global__ void __launch_bounds__(256) resid_ln_kernel(const float* __restrict__ skip,
                                                       const float* __restrict__ h,
                                                       const float* __restrict__ ao,
                                                       const float* __restrict__ gamma,
                                                       const float* __restrict__ beta,
                                                       float* __restrict__ out) {
    int i = blockIdx.x;
    int c = threadIdx.x;
    size_t o = (size_t)i*CC + c;
    float v = skip[o] + h[o] + ao[o];
    __shared__ float sred[256];
    sred[c] = v; __syncthreads();
#pragma unroll
    for (int s = 128; s; s >>= 1) { if (c < s) sred[c] += sred[c + s]; __syncthreads(); }
    float mean = sred[0] * (1.f/256.f); __syncthreads();
    float d = v - mean;
    sred[c] = d * d; __syncthreads();
#pragma unroll
    for (int s = 128; s; s >>= 1) { if (c < s) sred[c] += sred[c + s]; __syncthreads(); }
    float var = sred[0] * (1.f/256.f);
    out[o] = d * rsqrtf(var + 1e-5f) * gamma[c] + beta[c];
}

// ---------------- gate + skip + output head + softplus ----------------
__global__ void __launch_bounds__(256) final_kernel(const float* __restrict__ gpre,
                                                    const float* __restrict__ href,
                                                    const float* __restrict__ skip2,
                                                    const float* __restrict__ W_out,
                                                    const float* __restrict__ b_out,
                                                    float* __restrict__ out) {
    int i = blockIdx.x;
    int c = threadIdx.x;
    float g = 1.f / (1.f + expf(-gpre[(size_t)i*CC + c]));
    float hf = g * href[(size_t)i*CC + c] + (1.f - g) * skip2[(size_t)i*CC + c];
    __shared__ float r0[256], r1[256];
    r0[c] = hf * W_out[c*2 + 0];
    r1[c] = hf * W_out[c*2 + 1];
    __syncthreads();
#pragma unroll
    for (int s = 128; s; s >>= 1) {
        if (c < s) { r0[c] += r0[c + s]; r1[c] += r1[c + s]; }
        __syncthreads();
    }
    if (c == 0) {
        float o0 = r0[0] + b_out[0];
        float o1 = r1[0] + b_out[1];
        out[(size_t)i*2 + 0] = o0;
        out[(size_t)i*2 + 1] = fmaxf(o1, 0.f) + log1pf(expf(-fabsf(o1)));
    }
}

// ---------------- host orchestration ----------------
extern "C" void kernel_launch(void* const* d_in, const int* in_sizes, int n_in,
                              void* d_out, int out_size) {
    const float* x        = (const float*)d_in[0];
    const int*   edge     = (const int*)  d_in[1];
    const float* W_enc    = (const float*)d_in[2];
    const float* b_enc    = (const float*)d_in[3];
    const float* station  = (const float*)d_in[4];
    const float* horizon  = (const float*)d_in[5];
    const float* conv_w   = (const float*)d_in[6];
    const float* conv_b   = (const float*)d_in[7];
    const float* gat_wl   = (const float*)d_in[8];
    const float* gat_wr   = (const float*)d_in[9];
    const float* gat_att  = (const float*)d_in[10];
    const float* gat_b    = (const float*)d_in[11];
    const float* norm_g   = (const float*)d_in[12];
    const float* norm_b   = (const float*)d_in[13];
    const float* Wq       = (const float*)d_in[14];
    const float* Wk       = (const float*)d_in[15];
    const float* Wv       = (const float*)d_in[16];
    const float* Wo       = (const float*)d_in[17];
    const float* bq       = (const float*)d_in[18];
    const float* bk       = (const float*)d_in[19];
    const float* bv       = (const float*)d_in[20];
    const float* bo       = (const float*)d_in[21];
    const float* an_g     = (const float*)d_in[22];
    const float* an_b     = (const float*)d_in[23];
    const float* W_skip   = (const float*)d_in[24];
    const float* b_skip   = (const float*)d_in[25];
    const float* W_gate   = (const float*)d_in[26];
    const float* b_gate   = (const float*)d_in[27];
    const float* W_out    = (const float*)d_in[28];
    const float* b_out    = (const float*)d_in[29];
    float* out = (float*)d_out;

    float* buf = nullptr;
    cudaGetSymbolAddress((void**)&buf, d_buf);
    float2* wbuf2 = nullptr;
    cudaGetSymbolAddress((void**)&wbuf2, d_wbuf2);
    float* wbuf1 = nullptr;
    cudaGetSymbolAddress((void**)&wbuf1, d_wbuf1);

    float* g_h    = buf + OFF_H;
    float* g_h2   = buf + OFF_H2;
    float* g_skip = buf + OFF_SKIP;
    float* g_y    = buf + OFF_Y;
    float* g_xlr  = buf + OFF_XLR;
    float* g_qkv  = buf + OFF_QKV;
    float* g_ao   = buf + OFF_AO;
    float* g_href = buf + OFF_HREF;
    float* g_bqkv = buf + OFF_BQKV;

    float* w_wlr  = wbuf1 + WF_WLR;
    float* w_qkv  = wbuf1 + WF_QKV;
    float* w_enc  = wbuf1 + WF_ENC;
    float* w_skip = wbuf1 + WF_SKIP;
    float* w_wo   = wbuf1 + WF_WO;
    float* w_gate = wbuf1 + WF_GATE;

    const dim3 thr(256);
    const dim3 gN256(CC/64, NNODE/128);           // (4, 96)
    const dim3 gN768(768/64, NNODE/128);          // (12, 96)
    const dim3 gN1024(1024/64, NNODE/128);        // (16, 96)

    cudaFuncSetAttribute(mha_kernel, cudaFuncAttributeMaxDynamicSharedMemorySize, MHA_SMEM);
    cudaFuncSetAttribute(gat_fused_kernel, cudaFuncAttributeMaxDynamicSharedMemorySize,
                         GAT_SMEM);

    build_csr_kernel<<<1, NST>>>(edge);
    transpose_w_all<<<(LL*KK*CC*CC)/256, thr>>>(conv_w, wbuf2);
    pack_qkv_kernel<<<(CC*768)/256, thr>>>(Wq, Wk, Wv, bq, bk, bv, w_qkv, g_bqkv);
    pack_wlr_kernel<<<(LL*CC*1024)/256, thr>>>(gat_wl, gat_wr, w_wlr);
    prep_small<<<163840/256, thr>>>(W_enc, W_skip, Wo, W_gate, w_enc);

    // encoder: h = x @ W_enc + b_enc + station + horizon
    gemm_tc<1,0,0,0><<<gN256, thr>>>(x, nullptr, w_enc, b_enc, g_h, CC, FINF, 0, 0,
                                     nullptr, station, horizon);

    float* hcur = g_h;
    float* hnext = g_h2;
    for (int l = 0; l < LL; l++) {
        int dil = 1 << l;
        // conv keeps RNA A-rounding + 2-term B split (accuracy-critical spine)
        gemm_tc<3,1,1,1><<<gN256, thr>>>(hcur, nullptr, wbuf2 + (size_t)l*KK*CC*CC,
                                         conv_b + l*CC, hnext, CC, KK*CC, dil, l == 0,
                                         g_skip, nullptr, nullptr);
        gemm_tc<0,0,0,0><<<gN1024, thr>>>(hnext, nullptr, w_wlr + (size_t)l*CC*1024,
                                          nullptr, g_xlr, 1024, CC, 0, 0,
                                          nullptr, nullptr, nullptr);
        gat_fused_kernel<<<NNODE, thr, GAT_SMEM>>>(edge, g_xlr, gat_att + l*GHH*CC,
                                                   gat_b + l*CC, norm_g + l*CC,
                                                   norm_b + l*CC, hnext);
        float* tmp = hcur; hcur = hnext; hnext = tmp;
    }

    // QKV in one GEMM, A = skip + h (fused)
    gemm_tc<0,2,0,0><<<gN768, thr>>>(g_skip, hcur, w_qkv, g_bqkv, g_qkv, 768, CC, 0, 0,
                                     nullptr, nullptr, nullptr);
    mha_kernel<<<dim3(NHH, NG), thr, MHA_SMEM>>>(g_qkv, g_xlr);
    gemm_tc<0,0,0,0><<<gN256, thr>>>(g_xlr, nullptr, w_wo, bo, g_ao, CC, CC, 0, 0,
                                     nullptr, nullptr, nullptr);
    resid_ln_kernel<<<NNODE, thr>>>(g_skip, hcur, g_ao, an_g, an_b, g_href);

    // gate + skip branch + output head
    gemm_tc<0,0,0,0><<<gN256, thr>>>(x, nullptr, w_skip, b_skip, g_y, CC, FINF, 0, 0,
                                     nullptr, nullptr, nullptr);
    gemm_tc<0,0,0,0><<<gN256, thr>>>(g_href, nullptr, w_gate, b_gate, g_qkv, CC, CC, 0, 0,
                                     nullptr, nullptr, nullptr);
    final_kernel<<<NNODE, thr>>>(g_qkv, g_href, g_y, W_out, b_out, out);

    (void)in_sizes; (void)n_in; (void)out_size;
}